// round 5
// baseline (speedup 1.0000x reference)
#include <cuda_runtime.h>
#include <cuda_bf16.h>
#include <cstdint>

typedef __nv_bfloat16 bf16;

#define BSZ 64
#define TT  512
#define FF  1024
#define HH  1024
#define GG  4096
#define KK  1024
#define MTOT (TT*BSZ)   // 32768

// ---------------- device scratch (static allocations are allowed) ----------------
__device__ __align__(16) bf16  g_wih0[GG * 2 * KK];   // [G][hi(0:K) | lo(K:2K)]
__device__ __align__(16) bf16  g_whh0[GG * 2 * KK];
__device__ __align__(16) bf16  g_wih1[GG * 2 * KK];
__device__ __align__(16) bf16  g_whh1[GG * 2 * KK];
__device__ __align__(16) float g_bias0[GG];
__device__ __align__(16) float g_bias1[GG];
__device__ __align__(16) float g_gx[(size_t)MTOT * GG];   // gates_x for current layer (512 MB)
__device__ __align__(16) float g_h1[(size_t)MTOT * HH];   // layer-0 hidden states, all t (128 MB)
__device__ __align__(16) bf16  g_hs_hi[2][BSZ * HH];      // split h ping-pong (hi)
__device__ __align__(16) bf16  g_hs_lo[2][BSZ * HH];      // split h ping-pong (lo)

// grid-barrier state: monotonic, never reset (deterministic across graph replays)
__device__ volatile unsigned g_flags[128];
__device__ volatile unsigned g_release;

// ---------------- helpers ----------------
__device__ __forceinline__ unsigned pack2(bf16 a, bf16 b) {
    return (unsigned)__bfloat16_as_ushort(a) | ((unsigned)__bfloat16_as_ushort(b) << 16);
}

// exact split v = hi + r, lo = bf16(r); residual ~2^-17 * |v|
__device__ __forceinline__ void split2(float a, float b, unsigned &h, unsigned &l) {
    bf16 ha = __float2bfloat16(a);
    bf16 hb = __float2bfloat16(b);
    bf16 la = __float2bfloat16(a - __bfloat162float(ha));
    bf16 lb = __float2bfloat16(b - __bfloat162float(hb));
    h = pack2(ha, hb);
    l = pack2(la, lb);
}

__device__ __forceinline__ void mma_bf16(float acc[4], const unsigned a[4], const unsigned b[2]) {
    asm volatile(
        "mma.sync.aligned.m16n8k16.row.col.f32.bf16.bf16.f32 "
        "{%0,%1,%2,%3},{%4,%5,%6,%7},{%8,%9},{%0,%1,%2,%3};\n"
        : "+f"(acc[0]), "+f"(acc[1]), "+f"(acc[2]), "+f"(acc[3])
        : "r"(a[0]), "r"(a[1]), "r"(a[2]), "r"(a[3]), "r"(b[0]), "r"(b[1]));
}

__device__ __forceinline__ void ldsm4(unsigned r[4], const void* p) {
    unsigned addr = (unsigned)__cvta_generic_to_shared(p);
    asm volatile("ldmatrix.sync.aligned.m8n8.x4.shared.b16 {%0,%1,%2,%3},[%4];\n"
                 : "=r"(r[0]), "=r"(r[1]), "=r"(r[2]), "=r"(r[3]) : "r"(addr));
}

__device__ __forceinline__ float sigf(float x) { return 1.0f / (1.0f + expf(-x)); }

// grid-wide barrier: each CTA posts its flag=target; CTA0/warp0 aggregates and
// publishes g_release=target; everyone spins on g_release. target is monotonic.
__device__ __forceinline__ void grid_bar(int ch, int tid, unsigned target) {
    __syncthreads();
    if (tid == 0) {
        __threadfence();
        g_flags[ch] = target;
    }
    if (ch == 0 && tid < 32) {
        #pragma unroll
        for (int i = 0; i < 4; i++) {
            int idx = tid * 4 + i;
            while ((int)(g_flags[idx] - target) < 0) { }
        }
        __syncwarp();
        if (tid == 0) {
            __threadfence();
            g_release = target;
        }
    } else if (tid == 0) {
        while ((int)(g_release - target) < 0) { }
        __threadfence();
    }
    __syncthreads();
}

// ---------------- prep: masked weight -> bf16 hi/lo split ----------------
// NOTE: masks arrive as 32-bit elements (harness widens bool_ to int32/float32).
// A nonzero 32-bit word means "keep" for both encodings (1 and 1.0f).
__global__ void prep_w(const float* __restrict__ w, const unsigned* __restrict__ m, int which) {
    int idx = blockIdx.x * 256 + threadIdx.x;           // [0, G*K)
    if (idx >= GG * KK) return;
    bf16* dst = (which == 0) ? g_wih0 : (which == 1) ? g_whh0 : (which == 2) ? g_wih1 : g_whh1;
    int g = idx >> 10, k = idx & 1023;
    float v = (m[idx] != 0u) ? w[idx] : 0.0f;
    bf16 hi = __float2bfloat16(v);
    float r = v - __bfloat162float(hi);
    dst[(size_t)g * 2048 + k]        = hi;
    dst[(size_t)g * 2048 + 1024 + k] = __float2bfloat16(r);
}

__global__ void prep_bias(const float* __restrict__ a, const float* __restrict__ b, int layer) {
    int i = blockIdx.x * 256 + threadIdx.x;
    float* dst = layer ? g_bias1 : g_bias0;
    if (i < GG) dst[i] = a[i] + b[i];
}

// ---------------- big input GEMM: gates_x = A @ W^T (3-split) + bias ----------------
// A logical [32768, 1024] via (t,b) strides; W split [4096][2048]; C = g_gx row-major.
// CTA tile 128x128, 8 warps in 4(m) x 2(n); warp tile 32x64. 1-deep register prefetch.
__global__ __launch_bounds__(256) void xgemm(const float* __restrict__ Aext, int useExt,
                                             long sT, long sB, int layer) {
    __shared__ __align__(16) unsigned char sm[24576];
    bf16* Ah = (bf16*)(sm);            // [128][24]
    bf16* Al = (bf16*)(sm + 6144);
    bf16* Bh = (bf16*)(sm + 12288);    // [128][24]
    bf16* Bl = (bf16*)(sm + 18432);

    const float* A    = useExt ? Aext : g_h1;
    const bf16* W     = layer ? g_wih1 : g_wih0;
    const float* bias = layer ? g_bias1 : g_bias0;
    float* C = g_gx;

    const int tid  = threadIdx.x;
    const int warp = tid >> 5, lane = tid & 31;
    const int wm = warp & 3, wn = warp >> 2;
    const int mB = blockIdx.y, nB = blockIdx.x;

    float acc[2][8][4];
    #pragma unroll
    for (int i = 0; i < 2; i++)
        #pragma unroll
        for (int j = 0; j < 8; j++)
            #pragma unroll
            for (int k = 0; k < 4; k++) acc[i][j][k] = 0.0f;

    // global-load indices (each thread: 8 elems of one row per tile-k)
    const int lr = tid >> 1;             // row in tile [0,128)
    const int lc = (tid & 1) * 8;        // k offset 0 or 8
    const int am = mB * 128 + lr;
    const long abase = (long)(am >> 6) * sT + (long)(am & 63) * sB;
    const bf16* wrow = W + (size_t)(nB * 128 + lr) * 2048;

    // ldmatrix address components
    const int arb = (lane & 7) + ((lane >> 3) & 1) * 8;   // A row within 16-block
    const int ac  = (lane >> 4) * 8;                      // A col 0/8
    const int brb = (lane & 7) + ((lane >> 4) & 1) * 8;   // B row within 16-pair
    const int bc  = ((lane >> 3) & 1) * 8;                // B col 0/8

    // prefetch kt=0
    float4 av0 = *(const float4*)(A + abase + lc);
    float4 av1 = *(const float4*)(A + abase + lc + 4);
    uint4  bv0 = *(const uint4*)(wrow + lc);
    uint4  bv1 = *(const uint4*)(wrow + lc + 1024);

    for (int kt = 0; kt < 64; kt++) {
        {   // stage current tile into smem (A: fp32 -> hi/lo split)
            unsigned h0, h1, h2, h3, l0, l1, l2, l3;
            split2(av0.x, av0.y, h0, l0); split2(av0.z, av0.w, h1, l1);
            split2(av1.x, av1.y, h2, l2); split2(av1.z, av1.w, h3, l3);
            *(uint4*)(Ah + lr * 24 + lc) = make_uint4(h0, h1, h2, h3);
            *(uint4*)(Al + lr * 24 + lc) = make_uint4(l0, l1, l2, l3);
            *(uint4*)(Bh + lr * 24 + lc) = bv0;
            *(uint4*)(Bl + lr * 24 + lc) = bv1;
        }
        __syncthreads();

        if (kt + 1 < 64) {   // prefetch next tile (overlaps with mma below)
            const float* srcA = A + abase + (kt + 1) * 16 + lc;
            av0 = *(const float4*)(srcA);
            av1 = *(const float4*)(srcA + 4);
            const bf16* srcB = wrow + (kt + 1) * 16 + lc;
            bv0 = *(const uint4*)(srcB);
            bv1 = *(const uint4*)(srcB + 1024);
        }

        unsigned aF[2][2][4];   // [mb][hi/lo][4]
        #pragma unroll
        for (int mb = 0; mb < 2; mb++) {
            int r = wm * 32 + mb * 16 + arb;
            ldsm4(aF[mb][0], Ah + r * 24 + ac);
            ldsm4(aF[mb][1], Al + r * 24 + ac);
        }
        unsigned bF[8][2][2];   // [nb][hi/lo][2]
        #pragma unroll
        for (int p = 0; p < 4; p++) {
            int r = wn * 64 + p * 16 + brb;
            unsigned t[4];
            ldsm4(t, Bh + r * 24 + bc);
            bF[2*p][0][0]=t[0]; bF[2*p][0][1]=t[1]; bF[2*p+1][0][0]=t[2]; bF[2*p+1][0][1]=t[3];
            ldsm4(t, Bl + r * 24 + bc);
            bF[2*p][1][0]=t[0]; bF[2*p][1][1]=t[1]; bF[2*p+1][1][0]=t[2]; bF[2*p+1][1][1]=t[3];
        }
        #pragma unroll
        for (int mb = 0; mb < 2; mb++)
            #pragma unroll
            for (int nb = 0; nb < 8; nb++) {
                mma_bf16(acc[mb][nb], aF[mb][0], bF[nb][0]);  // hi*hi
                mma_bf16(acc[mb][nb], aF[mb][0], bF[nb][1]);  // hi*lo
                mma_bf16(acc[mb][nb], aF[mb][1], bF[nb][0]);  // lo*hi
            }
        __syncthreads();
    }

    // epilogue: + bias, store fp32
    #pragma unroll
    for (int mb = 0; mb < 2; mb++) {
        int r0 = mB * 128 + wm * 32 + mb * 16 + (lane >> 2);
        #pragma unroll
        for (int nb = 0; nb < 8; nb++) {
            int c0 = nB * 128 + wn * 64 + nb * 8 + 2 * (lane & 3);
            float b0 = bias[c0], b1 = bias[c0 + 1];
            size_t o0 = (size_t)r0 * GG + c0;
            size_t o1 = (size_t)(r0 + 8) * GG + c0;
            C[o0]     = acc[mb][nb][0] + b0;
            C[o0 + 1] = acc[mb][nb][1] + b1;
            C[o1]     = acc[mb][nb][2] + b0;
            C[o1 + 1] = acc[mb][nb][3] + b1;
        }
    }
}

// ---------------- persistent recurrence: all 512 timesteps of one layer ----------------
// 128 CTAs x 256 thr, all co-resident. CTA ch owns h-cols [ch*8, ch*8+8) -> 32 gate rows.
// Weights (32 rows, hi+lo) live in SMEM for the whole kernel (loaded once).
// Per step: A fragments loaded directly from gmem (split-bf16 h, mma register layout),
// B via ldmatrix from smem — NO syncthreads in the K-loop. c-state in registers.
#define WPITCH 1032   // 1024 + 8 pad (bank-conflict-free ldmatrix rows)
__global__ __launch_bounds__(256, 1) void recur(int layer, float* __restrict__ lastout) {
    extern __shared__ __align__(16) unsigned char sm[];
    bf16* sWh = (bf16*)sm;                          // [32][WPITCH] hi
    bf16* sWl = (bf16*)(sm + 32 * WPITCH * 2);      // [32][WPITCH] lo
    float* gs = (float*)(sm + 64 * WPITCH * 2);     // [64][33]

    const int tid  = threadIdx.x;
    const int warp = tid >> 5, lane = tid & 31;
    const int wm = warp & 3, wn = warp >> 2;        // 4(m=b) x 2(n=gate) warps
    const int ch = blockIdx.x;
    const int j0 = ch * 8;
    const bf16* W = layer ? g_whh1 : g_whh0;

    // load this CTA's weights into smem once
    for (int idx = tid; idx < 32 * 128; idx += 256) {
        int n = idx >> 7, u = idx & 127;            // n: local gate row, u: uint4 index
        int g = (n >> 3) * 1024 + j0 + (n & 7);
        *(uint4*)(sWh + n * WPITCH + u * 8) = *(const uint4*)(W + (size_t)g * 2048 + u * 8);
        *(uint4*)(sWl + n * WPITCH + u * 8) = *(const uint4*)(W + (size_t)g * 2048 + 1024 + u * 8);
    }
    __syncthreads();

    const unsigned base = g_release;   // stable: no CTA publishes until all arrived at bar 1

    // A-fragment gmem address components (mma m16n8k16 A layout, direct load)
    const int r0   = wm * 16 + (lane >> 2);
    const int ccol = 2 * (lane & 3);
    // B ldmatrix address components
    const int brow = wn * 16 + (lane & 7) + ((lane >> 4) & 1) * 8;
    const int bcc  = ((lane >> 3) & 1) * 8;
    const bf16* sWh_l = sWh + brow * WPITCH + bcc;
    const bf16* sWl_l = sWl + brow * WPITCH + bcc;

    float creg[2] = {0.0f, 0.0f};   // cell state, persistent in registers

    for (int t = 0; t < TT; t++) {
        // prefetch gates_x for this step (independent of the barrier)
        float gxv[2][4];
        #pragma unroll
        for (int it = 0; it < 2; it++) {
            int p = tid + it * 256;
            int b = p >> 3, jj = p & 7;
            size_t gxb = ((size_t)t * 64 + b) * GG + j0 + jj;
            gxv[it][0] = g_gx[gxb];
            gxv[it][1] = g_gx[gxb + 1024];
            gxv[it][2] = g_gx[gxb + 2048];
            gxv[it][3] = g_gx[gxb + 3072];
        }

        float acc[2][4] = {{0,0,0,0},{0,0,0,0}};
        if (t > 0) {
            const int rb = (t & 1) ^ 1;
            const bf16* hA = g_hs_hi[rb] + r0 * 1024 + ccol;
            const bf16* lA = g_hs_lo[rb] + r0 * 1024 + ccol;
            #pragma unroll 4
            for (int kt = 0; kt < 64; kt++) {
                const int off = kt * 16;
                unsigned aH[4], aL[4];
                aH[0] = *(const unsigned*)(hA + off);
                aH[1] = *(const unsigned*)(hA + off + 8192);
                aH[2] = *(const unsigned*)(hA + off + 8);
                aH[3] = *(const unsigned*)(hA + off + 8200);
                aL[0] = *(const unsigned*)(lA + off);
                aL[1] = *(const unsigned*)(lA + off + 8192);
                aL[2] = *(const unsigned*)(lA + off + 8);
                aL[3] = *(const unsigned*)(lA + off + 8200);
                unsigned bH[4], bL[4];
                ldsm4(bH, sWh_l + off);
                ldsm4(bL, sWl_l + off);
                unsigned b0h[2] = {bH[0], bH[1]}, b1h[2] = {bH[2], bH[3]};
                unsigned b0l[2] = {bL[0], bL[1]}, b1l[2] = {bL[2], bL[3]};
                mma_bf16(acc[0], aH, b0h);
                mma_bf16(acc[0], aH, b0l);
                mma_bf16(acc[0], aL, b0h);
                mma_bf16(acc[1], aH, b1h);
                mma_bf16(acc[1], aH, b1l);
                mma_bf16(acc[1], aL, b1h);
            }
        }

        // stage gate accumulators to smem [64][33]
        {
            int r = wm * 16 + (lane >> 2);
            #pragma unroll
            for (int nb = 0; nb < 2; nb++) {
                int c = wn * 16 + nb * 8 + 2 * (lane & 3);
                gs[r * 33 + c]           = acc[nb][0];
                gs[r * 33 + c + 1]       = acc[nb][1];
                gs[(r + 8) * 33 + c]     = acc[nb][2];
                gs[(r + 8) * 33 + c + 1] = acc[nb][3];
            }
        }
        __syncthreads();

        // LSTM elementwise + h write (split bf16, plus fp32 history for layer 0)
        const int wb = t & 1;
        #pragma unroll
        for (int it = 0; it < 2; it++) {
            int p = tid + it * 256;
            int b = p >> 3, jj = p & 7;
            float gi = gs[b * 33 + jj]      + gxv[it][0];
            float gf = gs[b * 33 + 8 + jj]  + gxv[it][1];
            float gg = gs[b * 33 + 16 + jj] + gxv[it][2];
            float go = gs[b * 33 + 24 + jj] + gxv[it][3];
            float i = sigf(gi), f = sigf(gf), g = tanhf(gg), o = sigf(go);
            float cn = f * creg[it] + i * g;
            float hn = o * tanhf(cn);
            creg[it] = cn;
            int hidx = b * HH + j0 + jj;
            bf16 hh = __float2bfloat16(hn);
            g_hs_hi[wb][hidx] = hh;
            g_hs_lo[wb][hidx] = __float2bfloat16(hn - __bfloat162float(hh));
            if (layer == 0) {
                g_h1[(size_t)t * (BSZ * HH) + hidx] = hn;
            } else if (t == TT - 1) {
                lastout[hidx] = hn;
            }
        }

        // grid barrier: h[t] fully published before any CTA reads it at t+1
        grid_bar(ch, tid, base + (unsigned)t + 1u);
    }
}

// ---------------- host launcher ----------------
extern "C" void kernel_launch(void* const* d_in, const int* in_sizes, int n_in,
                              void* d_out, int out_size) {
    (void)in_sizes; (void)n_in; (void)out_size;
    const float* x     = (const float*)d_in[0];
    const float* w_ih0 = (const float*)d_in[1];
    const float* w_hh0 = (const float*)d_in[2];
    const float* b_ih0 = (const float*)d_in[3];
    const float* b_hh0 = (const float*)d_in[4];
    const float* w_ih1 = (const float*)d_in[5];
    const float* w_hh1 = (const float*)d_in[6];
    const float* b_ih1 = (const float*)d_in[7];
    const float* b_hh1 = (const float*)d_in[8];
    const unsigned* m_ih0 = (const unsigned*)d_in[9];
    const unsigned* m_hh0 = (const unsigned*)d_in[10];
    const unsigned* m_ih1 = (const unsigned*)d_in[11];
    const unsigned* m_hh1 = (const unsigned*)d_in[12];
    float* out = (float*)d_out;

    const int recurSmem = 64 * WPITCH * 2 + 64 * 33 * 4;   // 132096 + 8448 = 140544
    cudaFuncSetAttribute(recur, cudaFuncAttributeMaxDynamicSharedMemorySize, recurSmem);

    const int pwGrid = (GG * KK + 255) / 256;   // 16384
    prep_w<<<pwGrid, 256>>>(w_ih0, m_ih0, 0);
    prep_w<<<pwGrid, 256>>>(w_hh0, m_hh0, 1);
    prep_w<<<pwGrid, 256>>>(w_ih1, m_ih1, 2);
    prep_w<<<pwGrid, 256>>>(w_hh1, m_hh1, 3);
    prep_bias<<<16, 256>>>(b_ih0, b_hh0, 0);
    prep_bias<<<16, 256>>>(b_ih1, b_hh1, 1);

    dim3 gemmGrid(GG / 128, MTOT / 128);  // (32, 256)

    // layer 0: x is [B, T, F] -> m=(t,b): sT = F, sB = T*F
    xgemm<<<gemmGrid, 256>>>(x, 1, (long)FF, (long)TT * FF, 0);
    recur<<<128, 256, recurSmem>>>(0, nullptr);

    // layer 1: A = g_h1, [T*B, H] contiguous -> sT = B*H, sB = H
    xgemm<<<gemmGrid, 256>>>(nullptr, 0, (long)BSZ * HH, (long)HH, 1);
    recur<<<128, 256, recurSmem>>>(1, out);
}

// round 7
// speedup vs baseline: 1.2814x; 1.2814x over previous
#include <cuda_runtime.h>
#include <cuda_bf16.h>
#include <cstdint>

typedef __nv_bfloat16 bf16;

#define BSZ 64
#define TT  512
#define FF  1024
#define HH  1024
#define GG  4096
#define KK  1024
#define MTOT (TT*BSZ)   // 32768

// ---------------- device scratch ----------------
__device__ __align__(16) bf16  g_wih0[GG * 2 * KK];   // [G][hi(0:K) | lo(K:2K)]
__device__ __align__(16) bf16  g_whh0[GG * 2 * KK];
__device__ __align__(16) bf16  g_wih1[GG * 2 * KK];
__device__ __align__(16) bf16  g_whh1[GG * 2 * KK];
__device__ __align__(16) float g_bias0[GG];
__device__ __align__(16) float g_bias1[GG];
__device__ __align__(16) float g_gx[(size_t)MTOT * GG];     // gates_x (512 MB)
__device__ __align__(16) bf16  g_ax[(size_t)MTOT * 2 * KK]; // split A for xgemm (128 MB)
// h in mma-fragment layout: [ping][ (hi:0 / lo:+32768) ][wm(4)][kt(64)][pair(2)][lane(32)][rh(2)] u32
__device__ __align__(16) unsigned g_hf[2][65536];

// grid-barrier flags: monotonic, never reset (deterministic across graph replays)
__device__ volatile unsigned g_flags[128];

// ---------------- helpers ----------------
__device__ __forceinline__ unsigned pack2(bf16 a, bf16 b) {
    return (unsigned)__bfloat16_as_ushort(a) | ((unsigned)__bfloat16_as_ushort(b) << 16);
}

// exact split v = hi + r, lo = bf16(r)
__device__ __forceinline__ void split2(float a, float b, unsigned &h, unsigned &l) {
    bf16 ha = __float2bfloat16(a);
    bf16 hb = __float2bfloat16(b);
    bf16 la = __float2bfloat16(a - __bfloat162float(ha));
    bf16 lb = __float2bfloat16(b - __bfloat162float(hb));
    h = pack2(ha, hb);
    l = pack2(la, lb);
}

__device__ __forceinline__ void mma_bf16(float acc[4], const unsigned a[4], const unsigned b[2]) {
    asm volatile(
        "mma.sync.aligned.m16n8k16.row.col.f32.bf16.bf16.f32 "
        "{%0,%1,%2,%3},{%4,%5,%6,%7},{%8,%9},{%0,%1,%2,%3};\n"
        : "+f"(acc[0]), "+f"(acc[1]), "+f"(acc[2]), "+f"(acc[3])
        : "r"(a[0]), "r"(a[1]), "r"(a[2]), "r"(a[3]), "r"(b[0]), "r"(b[1]));
}

__device__ __forceinline__ void ldsm4(unsigned r[4], const void* p) {
    unsigned addr = (unsigned)__cvta_generic_to_shared(p);
    asm volatile("ldmatrix.sync.aligned.m8n8.x4.shared.b16 {%0,%1,%2,%3},[%4];\n"
                 : "=r"(r[0]), "=r"(r[1]), "=r"(r[2]), "=r"(r[3]) : "r"(addr));
}

__device__ __forceinline__ void cpa16(void* dst, const void* src) {
    unsigned d = (unsigned)__cvta_generic_to_shared(dst);
    asm volatile("cp.async.cg.shared.global [%0], [%1], 16;\n" :: "r"(d), "l"(src));
}
#define CPCOMMIT() asm volatile("cp.async.commit_group;\n")
#define CPWAIT(n)  asm volatile("cp.async.wait_group %0;\n" :: "n"(n))

__device__ __forceinline__ float sigf(float x) { return 1.0f / (1.0f + expf(-x)); }

// ---------------- prep: masked weight -> bf16 hi/lo split ----------------
// masks arrive as 32-bit elements; nonzero word = keep.
__global__ void prep_w(const float* __restrict__ w, const unsigned* __restrict__ m, int which) {
    int idx = blockIdx.x * 256 + threadIdx.x;
    if (idx >= GG * KK) return;
    bf16* dst = (which == 0) ? g_wih0 : (which == 1) ? g_whh0 : (which == 2) ? g_wih1 : g_whh1;
    int g = idx >> 10, k = idx & 1023;
    float v = (m[idx] != 0u) ? w[idx] : 0.0f;
    bf16 hi = __float2bfloat16(v);
    float r = v - __bfloat162float(hi);
    dst[(size_t)g * 2048 + k]        = hi;
    dst[(size_t)g * 2048 + 1024 + k] = __float2bfloat16(r);
}

__global__ void prep_bias(const float* __restrict__ a, const float* __restrict__ b, int layer) {
    int i = blockIdx.x * 256 + threadIdx.x;
    float* dst = layer ? g_bias1 : g_bias0;
    if (i < GG) dst[i] = a[i] + b[i];
}

// ---------------- prep: x -> g_ax split rows (m = t*64 + b) ----------------
__global__ void prep_ax(const float* __restrict__ x) {
    int m = blockIdx.x * 2 + (threadIdx.x >> 7);
    int c = (threadIdx.x & 127) * 8;
    const float* src = x + ((size_t)(m & 63) * TT + (m >> 6)) * FF + c;
    float4 v0 = *(const float4*)src;
    float4 v1 = *(const float4*)(src + 4);
    unsigned h0, h1, h2, h3, l0, l1, l2, l3;
    split2(v0.x, v0.y, h0, l0); split2(v0.z, v0.w, h1, l1);
    split2(v1.x, v1.y, h2, l2); split2(v1.z, v1.w, h3, l3);
    bf16* d = g_ax + (size_t)m * 2048 + c;
    *(uint4*)d          = make_uint4(h0, h1, h2, h3);
    *(uint4*)(d + 1024) = make_uint4(l0, l1, l2, l3);
}

// ---------------- big input GEMM: gates_x = A @ W^T + bias ----------------
// A = g_ax [32768][2048] split bf16; W split [4096][2048]; C = g_gx fp32.
// CTA tile 128x128, 8 warps 4(m)x2(n), warp tile 32x64.
// K chunks of 64 (128-B rows), cp.async double-buffered.
#define XP 72                 // smem row pitch (bf16)
#define XBUF (128 * XP)       // one buffer (elems)
#define XSTAGE (4 * XBUF)     // Ah,Al,Bh,Bl
#define XSMEM (2 * XSTAGE * 2)  // bytes = 147456

__device__ __forceinline__ void xload(bf16* st, const bf16* Abase, const bf16* Bbase,
                                      int ck, int tid) {
    #pragma unroll
    for (int i = 0; i < 4; i++) {
        int j = tid + i * 256;                 // [0,1024)
        int row = j >> 3, seg = j & 7;
        const bf16* as = Abase + (size_t)row * 2048 + ck * 64 + seg * 8;
        const bf16* bs = Bbase + (size_t)row * 2048 + ck * 64 + seg * 8;
        bf16* d = st + row * XP + seg * 8;
        cpa16(d,            as);
        cpa16(d + XBUF,     as + 1024);
        cpa16(d + 2*XBUF,   bs);
        cpa16(d + 3*XBUF,   bs + 1024);
    }
}

__global__ __launch_bounds__(256) void xgemm(int layer) {
    extern __shared__ __align__(16) bf16 xs[];
    const bf16* W     = layer ? g_wih1 : g_wih0;
    const float* bias = layer ? g_bias1 : g_bias0;

    const int tid  = threadIdx.x;
    const int warp = tid >> 5, lane = tid & 31;
    const int wm = warp & 3, wn = warp >> 2;
    const int mB = blockIdx.y, nB = blockIdx.x;
    const bf16* Abase = g_ax + (size_t)(mB * 128) * 2048;
    const bf16* Bbase = W    + (size_t)(nB * 128) * 2048;

    float acc[2][8][4] = {};

    const int arb = (lane & 7) + ((lane >> 3) & 1) * 8;
    const int ac  = (lane >> 4) * 8;
    const int brb = (lane & 7) + ((lane >> 4) & 1) * 8;
    const int bc  = ((lane >> 3) & 1) * 8;

    xload(xs, Abase, Bbase, 0, tid); CPCOMMIT();

    for (int ck = 0; ck < 16; ck++) {
        const int s = ck & 1;
        if (ck + 1 < 16) { xload(xs + (s ^ 1) * XSTAGE, Abase, Bbase, ck + 1, tid); CPCOMMIT(); CPWAIT(1); }
        else             { CPWAIT(0); }
        __syncthreads();

        bf16* Ah = xs + s * XSTAGE;
        bf16* Al = Ah + XBUF;
        bf16* Bh = Al + XBUF;
        bf16* Bl = Bh + XBUF;

        #pragma unroll
        for (int k4 = 0; k4 < 4; k4++) {
            const int co = k4 * 16;
            unsigned aF[2][2][4];
            #pragma unroll
            for (int mb = 0; mb < 2; mb++) {
                int r = wm * 32 + mb * 16 + arb;
                ldsm4(aF[mb][0], Ah + r * XP + co + ac);
                ldsm4(aF[mb][1], Al + r * XP + co + ac);
            }
            unsigned bF[8][2][2];
            #pragma unroll
            for (int p = 0; p < 4; p++) {
                int r = wn * 64 + p * 16 + brb;
                unsigned t[4];
                ldsm4(t, Bh + r * XP + co + bc);
                bF[2*p][0][0]=t[0]; bF[2*p][0][1]=t[1]; bF[2*p+1][0][0]=t[2]; bF[2*p+1][0][1]=t[3];
                ldsm4(t, Bl + r * XP + co + bc);
                bF[2*p][1][0]=t[0]; bF[2*p][1][1]=t[1]; bF[2*p+1][1][0]=t[2]; bF[2*p+1][1][1]=t[3];
            }
            #pragma unroll
            for (int mb = 0; mb < 2; mb++)
                #pragma unroll
                for (int nb = 0; nb < 8; nb++) {
                    mma_bf16(acc[mb][nb], aF[mb][0], bF[nb][0]);  // hi*hi
                    mma_bf16(acc[mb][nb], aF[mb][0], bF[nb][1]);  // hi*lo
                    mma_bf16(acc[mb][nb], aF[mb][1], bF[nb][0]);  // lo*hi
                }
        }
        __syncthreads();
    }

    #pragma unroll
    for (int mb = 0; mb < 2; mb++) {
        int r0 = mB * 128 + wm * 32 + mb * 16 + (lane >> 2);
        #pragma unroll
        for (int nb = 0; nb < 8; nb++) {
            int c0 = nB * 128 + wn * 64 + nb * 8 + 2 * (lane & 3);
            float b0 = bias[c0], b1 = bias[c0 + 1];
            size_t o0 = (size_t)r0 * GG + c0;
            size_t o1 = (size_t)(r0 + 8) * GG + c0;
            g_gx[o0]     = acc[mb][nb][0] + b0;
            g_gx[o0 + 1] = acc[mb][nb][1] + b1;
            g_gx[o1]     = acc[mb][nb][2] + b0;
            g_gx[o1 + 1] = acc[mb][nb][3] + b1;
        }
    }
}

// ---------------- persistent recurrence ----------------
// 128 CTAs x 256 thr. CTA ch owns h-cols [ch*8, ch*8+8) -> 32 gate rows in SMEM.
// h stored in g_hf fragment layout -> fully coalesced A loads, no sync in K-loop.
// idx(hiLo,wm,kt,pair,lane,rh) = hiLo*32768 + wm*8192 + kt*128 + pair*64 + lane*2 + rh
#define WPITCH 1032
__global__ __launch_bounds__(256, 1) void recur(int layer, float* __restrict__ lastout) {
    extern __shared__ __align__(16) unsigned char sm[];
    bf16* sWh = (bf16*)sm;                          // [32][WPITCH] hi
    bf16* sWl = (bf16*)(sm + 32 * WPITCH * 2);      // [32][WPITCH] lo
    float* gs = (float*)(sm + 64 * WPITCH * 2);     // [64][33]
    __shared__ unsigned sbase;

    const int tid  = threadIdx.x;
    const int warp = tid >> 5, lane = tid & 31;
    const int wm = warp & 3, wn = warp >> 2;
    const int ch = blockIdx.x;
    const int j0 = ch * 8;
    const bf16* W = layer ? g_whh1 : g_whh0;

    for (int idx = tid; idx < 32 * 128; idx += 256) {
        int n = idx >> 7, u = idx & 127;
        int g = (n >> 3) * 1024 + j0 + (n & 7);
        *(uint4*)(sWh + n * WPITCH + u * 8) = *(const uint4*)(W + (size_t)g * 2048 + u * 8);
        *(uint4*)(sWl + n * WPITCH + u * 8) = *(const uint4*)(W + (size_t)g * 2048 + 1024 + u * 8);
    }
    if (tid == 0) sbase = g_flags[ch];
    __syncthreads();
    const unsigned base = sbase;

    // consumer (GEMM) indices
    const int cbase = wm * 8192 + lane * 2;
    const int brow = wn * 16 + (lane & 7) + ((lane >> 4) & 1) * 8;
    const int bcc  = ((lane >> 3) & 1) * 8;
    const bf16* sWh_l = sWh + brow * WPITCH + bcc;
    const bf16* sWl_l = sWl + brow * WPITCH + bcc;

    // writer (elementwise) indices: thread -> (b, col, col+1)
    const int b  = tid >> 2;
    const int jp = tid & 3;
    const int col = j0 + 2 * jp;
    const int widx = (b >> 4) * 8192 + (col >> 4) * 128 + ((col >> 3) & 1) * 64
                   + (((b & 7) << 2) | jp) * 2 + ((b >> 3) & 1);

    float c0 = 0.0f, c1 = 0.0f;   // cell state (2 cells/thread)

    for (int t = 0; t < TT; t++) {
        const float* gx = g_gx + ((size_t)t * 64 + b) * GG + col;
        float2 gx0 = *(const float2*)(gx);
        float2 gx1 = *(const float2*)(gx + 1024);
        float2 gx2 = *(const float2*)(gx + 2048);
        float2 gx3 = *(const float2*)(gx + 3072);

        float acc[2][4] = {{0,0,0,0},{0,0,0,0}};
        if (t > 0) {
            const unsigned* hf = g_hf[(t & 1) ^ 1];
            #pragma unroll 4
            for (int kt = 0; kt < 64; kt++) {
                const int ix = cbase + kt * 128;
                uint2 a01 = *(const uint2*)(hf + ix);            // pair0: rh0, rh1
                uint2 a23 = *(const uint2*)(hf + ix + 64);       // pair1
                uint2 l01 = *(const uint2*)(hf + ix + 32768);
                uint2 l23 = *(const uint2*)(hf + ix + 32768 + 64);
                unsigned aH[4] = {a01.x, a01.y, a23.x, a23.y};
                unsigned aL[4] = {l01.x, l01.y, l23.x, l23.y};
                unsigned bH[4], bL[4];
                ldsm4(bH, sWh_l + kt * 16);
                ldsm4(bL, sWl_l + kt * 16);
                unsigned b0h[2] = {bH[0], bH[1]}, b1h[2] = {bH[2], bH[3]};
                unsigned b0l[2] = {bL[0], bL[1]}, b1l[2] = {bL[2], bL[3]};
                mma_bf16(acc[0], aH, b0h);
                mma_bf16(acc[0], aH, b0l);
                mma_bf16(acc[0], aL, b0h);
                mma_bf16(acc[1], aH, b1h);
                mma_bf16(acc[1], aH, b1l);
                mma_bf16(acc[1], aL, b1h);
            }
        }

        // stage gate accumulators to smem [64][33]
        {
            int r = wm * 16 + (lane >> 2);
            #pragma unroll
            for (int nb = 0; nb < 2; nb++) {
                int c = wn * 16 + nb * 8 + 2 * (lane & 3);
                gs[r * 33 + c]           = acc[nb][0];
                gs[r * 33 + c + 1]       = acc[nb][1];
                gs[(r + 8) * 33 + c]     = acc[nb][2];
                gs[(r + 8) * 33 + c + 1] = acc[nb][3];
            }
        }
        __syncthreads();

        // LSTM elementwise: 2 cells per thread (cols col, col+1)
        {
            float gi0 = gs[b * 33 + 2*jp]          + gx0.x;
            float gi1 = gs[b * 33 + 2*jp + 1]      + gx0.y;
            float gf0 = gs[b * 33 + 8 + 2*jp]      + gx1.x;
            float gf1 = gs[b * 33 + 8 + 2*jp + 1]  + gx1.y;
            float gg0 = gs[b * 33 + 16 + 2*jp]     + gx2.x;
            float gg1 = gs[b * 33 + 16 + 2*jp + 1] + gx2.y;
            float go0 = gs[b * 33 + 24 + 2*jp]     + gx3.x;
            float go1 = gs[b * 33 + 24 + 2*jp + 1] + gx3.y;

            float i0 = sigf(gi0), f0 = sigf(gf0), G0 = tanhf(gg0), o0 = sigf(go0);
            float i1 = sigf(gi1), f1 = sigf(gf1), G1 = tanhf(gg1), o1 = sigf(go1);
            c0 = f0 * c0 + i0 * G0;
            c1 = f1 * c1 + i1 * G1;
            float hn0 = o0 * tanhf(c0);
            float hn1 = o1 * tanhf(c1);

            bf16 h0h = __float2bfloat16(hn0);
            bf16 h1h = __float2bfloat16(hn1);
            unsigned hiw = pack2(h0h, h1h);
            unsigned low = pack2(__float2bfloat16(hn0 - __bfloat162float(h0h)),
                                 __float2bfloat16(hn1 - __bfloat162float(h1h)));
            unsigned* dst = (unsigned*)g_hf[t & 1];
            dst[widx]         = hiw;
            dst[widx + 32768] = low;
            if (layer == 0) {
                bf16* ax = g_ax + ((size_t)t * 64 + b) * 2048 + col;
                *(unsigned*)ax          = hiw;
                *(unsigned*)(ax + 1024) = low;
            } else if (t == TT - 1) {
                lastout[b * HH + col]     = hn0;
                lastout[b * HH + col + 1] = hn1;
            }
        }
        __threadfence();   // release: this thread's h writes visible GPU-wide

        // all-to-all grid barrier (monotonic targets)
        __syncthreads();
        const unsigned target = base + (unsigned)t + 1u;
        if (tid == 0) g_flags[ch] = target;
        if (tid < 128) {
            while ((int)(g_flags[tid] - target) < 0) __nanosleep(64);
        }
        __syncthreads();
        __threadfence();   // acquire: invalidate L1 so next-step h reads are fresh
    }
}

// ---------------- host launcher ----------------
extern "C" void kernel_launch(void* const* d_in, const int* in_sizes, int n_in,
                              void* d_out, int out_size) {
    (void)in_sizes; (void)n_in; (void)out_size;
    const float* x     = (const float*)d_in[0];
    const float* w_ih0 = (const float*)d_in[1];
    const float* w_hh0 = (const float*)d_in[2];
    const float* b_ih0 = (const float*)d_in[3];
    const float* b_hh0 = (const float*)d_in[4];
    const float* w_ih1 = (const float*)d_in[5];
    const float* w_hh1 = (const float*)d_in[6];
    const float* b_ih1 = (const float*)d_in[7];
    const float* b_hh1 = (const float*)d_in[8];
    const unsigned* m_ih0 = (const unsigned*)d_in[9];
    const unsigned* m_hh0 = (const unsigned*)d_in[10];
    const unsigned* m_ih1 = (const unsigned*)d_in[11];
    const unsigned* m_hh1 = (const unsigned*)d_in[12];
    float* out = (float*)d_out;

    const int recurSmem = 64 * WPITCH * 2 + 64 * 33 * 4;   // 140544
    cudaFuncSetAttribute(recur, cudaFuncAttributeMaxDynamicSharedMemorySize, recurSmem);
    cudaFuncSetAttribute(xgemm, cudaFuncAttributeMaxDynamicSharedMemorySize, XSMEM);

    const int pwGrid = (GG * KK + 255) / 256;
    prep_w<<<pwGrid, 256>>>(w_ih0, m_ih0, 0);
    prep_w<<<pwGrid, 256>>>(w_hh0, m_hh0, 1);
    prep_w<<<pwGrid, 256>>>(w_ih1, m_ih1, 2);
    prep_w<<<pwGrid, 256>>>(w_hh1, m_hh1, 3);
    prep_bias<<<16, 256>>>(b_ih0, b_hh0, 0);
    prep_bias<<<16, 256>>>(b_ih1, b_hh1, 1);
    prep_ax<<<MTOT / 2, 256>>>(x);

    dim3 gemmGrid(GG / 128, MTOT / 128);   // (32, 256)

    xgemm<<<gemmGrid, 256, XSMEM>>>(0);
    recur<<<128, 256, recurSmem>>>(0, nullptr);   // also writes g_ax for layer 1

    xgemm<<<gemmGrid, 256, XSMEM>>>(1);
    recur<<<128, 256, recurSmem>>>(1, out);
}

// round 8
// speedup vs baseline: 1.4192x; 1.1075x over previous
#include <cuda_runtime.h>
#include <cuda_bf16.h>
#include <cstdint>

typedef __nv_bfloat16 bf16;

#define BSZ 64
#define TT  512
#define FF  1024
#define HH  1024
#define GG  4096
#define KK  1024
#define MTOT (TT*BSZ)   // 32768

// ---------------- device scratch ----------------
__device__ __align__(16) bf16  g_wih0[GG * 2 * KK];   // [G][hi(0:K) | lo(K:2K)]
__device__ __align__(16) bf16  g_whh0[GG * 2 * KK];
__device__ __align__(16) bf16  g_wih1[GG * 2 * KK];
__device__ __align__(16) bf16  g_whh1[GG * 2 * KK];
__device__ __align__(16) float g_bias0[GG];
__device__ __align__(16) float g_bias1[GG];
__device__ __align__(16) float g_gx[(size_t)MTOT * GG];     // gates_x (512 MB)
__device__ __align__(16) bf16  g_ax[(size_t)MTOT * 2 * KK]; // split A for xgemm (128 MB)
// h in mma-fragment layout v2:
//   u32 idx(hiLo, wm, kt, lane, reg) = hiLo*32768 + wm*8192 + kt*128 + lane*4 + reg
__device__ __align__(16) unsigned g_hf[2][65536];

// grid-barrier flags: monotonic, never reset (deterministic across graph replays)
__device__ volatile unsigned g_flags[128];

// ---------------- helpers ----------------
__device__ __forceinline__ unsigned pack2(bf16 a, bf16 b) {
    return (unsigned)__bfloat16_as_ushort(a) | ((unsigned)__bfloat16_as_ushort(b) << 16);
}

// exact split v = hi + r, lo = bf16(r)
__device__ __forceinline__ void split2(float a, float b, unsigned &h, unsigned &l) {
    bf16 ha = __float2bfloat16(a);
    bf16 hb = __float2bfloat16(b);
    bf16 la = __float2bfloat16(a - __bfloat162float(ha));
    bf16 lb = __float2bfloat16(b - __bfloat162float(hb));
    h = pack2(ha, hb);
    l = pack2(la, lb);
}

__device__ __forceinline__ void mma_bf16(float acc[4], const unsigned a[4], const unsigned b[2]) {
    asm volatile(
        "mma.sync.aligned.m16n8k16.row.col.f32.bf16.bf16.f32 "
        "{%0,%1,%2,%3},{%4,%5,%6,%7},{%8,%9},{%0,%1,%2,%3};\n"
        : "+f"(acc[0]), "+f"(acc[1]), "+f"(acc[2]), "+f"(acc[3])
        : "r"(a[0]), "r"(a[1]), "r"(a[2]), "r"(a[3]), "r"(b[0]), "r"(b[1]));
}

__device__ __forceinline__ void ldsm4(unsigned r[4], const void* p) {
    unsigned addr = (unsigned)__cvta_generic_to_shared(p);
    asm volatile("ldmatrix.sync.aligned.m8n8.x4.shared.b16 {%0,%1,%2,%3},[%4];\n"
                 : "=r"(r[0]), "=r"(r[1]), "=r"(r[2]), "=r"(r[3]) : "r"(addr));
}

// L1-bypass vector load (h ping-pong: L2 is the coherence point)
__device__ __forceinline__ void ldg_cg4(unsigned r[4], const void* p) {
    asm volatile("ld.global.cg.v4.u32 {%0,%1,%2,%3}, [%4];\n"
                 : "=r"(r[0]), "=r"(r[1]), "=r"(r[2]), "=r"(r[3]) : "l"(p));
}

__device__ __forceinline__ void st_rel(volatile unsigned* p, unsigned v) {
    asm volatile("st.release.gpu.global.u32 [%0], %1;\n" :: "l"((void*)p), "r"(v) : "memory");
}
__device__ __forceinline__ unsigned ld_acq(volatile unsigned* p) {
    unsigned v;
    asm volatile("ld.acquire.gpu.global.u32 %0, [%1];\n" : "=r"(v) : "l"((void*)p) : "memory");
    return v;
}

__device__ __forceinline__ void cpa16(void* dst, const void* src) {
    unsigned d = (unsigned)__cvta_generic_to_shared(dst);
    asm volatile("cp.async.cg.shared.global [%0], [%1], 16;\n" :: "r"(d), "l"(src));
}
#define CPCOMMIT() asm volatile("cp.async.commit_group;\n")
#define CPWAIT(n)  asm volatile("cp.async.wait_group %0;\n" :: "n"(n))

__device__ __forceinline__ float sigf(float x) { return 1.0f / (1.0f + expf(-x)); }

// ---------------- prep: all weights + biases in ONE launch ----------------
// blocks [0, 65536): weight elements (which = blk>>14); block 65536: biases.
// masks arrive as 32-bit elements; nonzero word = keep.
__global__ void prep_all(const float* __restrict__ w0, const unsigned* __restrict__ m0,
                         const float* __restrict__ w1, const unsigned* __restrict__ m1,
                         const float* __restrict__ w2, const unsigned* __restrict__ m2,
                         const float* __restrict__ w3, const unsigned* __restrict__ m3,
                         const float* __restrict__ bi0, const float* __restrict__ bh0,
                         const float* __restrict__ bi1, const float* __restrict__ bh1) {
    int blk = blockIdx.x;
    if (blk < 65536) {
        int which = blk >> 14;
        int idx = (blk & 16383) * 256 + threadIdx.x;
        const float*    w = (which == 0) ? w0 : (which == 1) ? w1 : (which == 2) ? w2 : w3;
        const unsigned* m = (which == 0) ? m0 : (which == 1) ? m1 : (which == 2) ? m2 : m3;
        bf16* dst = (which == 0) ? g_wih0 : (which == 1) ? g_whh0 : (which == 2) ? g_wih1 : g_whh1;
        int g = idx >> 10, k = idx & 1023;
        float v = (m[idx] != 0u) ? w[idx] : 0.0f;
        bf16 hi = __float2bfloat16(v);
        float r = v - __bfloat162float(hi);
        dst[(size_t)g * 2048 + k]        = hi;
        dst[(size_t)g * 2048 + 1024 + k] = __float2bfloat16(r);
    } else {
        for (int i = threadIdx.x; i < GG; i += 256) {
            g_bias0[i] = bi0[i] + bh0[i];
            g_bias1[i] = bi1[i] + bh1[i];
        }
    }
}

// ---------------- prep: x -> g_ax split rows (m = t*64 + b) ----------------
__global__ void prep_ax(const float* __restrict__ x) {
    int m = blockIdx.x * 2 + (threadIdx.x >> 7);
    int c = (threadIdx.x & 127) * 8;
    const float* src = x + ((size_t)(m & 63) * TT + (m >> 6)) * FF + c;
    float4 v0 = *(const float4*)src;
    float4 v1 = *(const float4*)(src + 4);
    unsigned h0, h1, h2, h3, l0, l1, l2, l3;
    split2(v0.x, v0.y, h0, l0); split2(v0.z, v0.w, h1, l1);
    split2(v1.x, v1.y, h2, l2); split2(v1.z, v1.w, h3, l3);
    bf16* d = g_ax + (size_t)m * 2048 + c;
    *(uint4*)d          = make_uint4(h0, h1, h2, h3);
    *(uint4*)(d + 1024) = make_uint4(l0, l1, l2, l3);
}

// ---------------- big input GEMM: gates_x = A @ W^T + bias ----------------
// A = g_ax [32768][2048] split bf16; W split [4096][2048]; C = g_gx fp32.
// CTA tile 128x128, 8 warps 4(m)x2(n), warp tile 32x64.
// K chunks of 64 (128-B rows), cp.async double-buffered.
#define XP 72                 // smem row pitch (bf16)
#define XBUF (128 * XP)       // one buffer (elems)
#define XSTAGE (4 * XBUF)     // Ah,Al,Bh,Bl
#define XSMEM (2 * XSTAGE * 2)  // bytes = 147456

__device__ __forceinline__ void xload(bf16* st, const bf16* Abase, const bf16* Bbase,
                                      int ck, int tid) {
    #pragma unroll
    for (int i = 0; i < 4; i++) {
        int j = tid + i * 256;                 // [0,1024)
        int row = j >> 3, seg = j & 7;
        const bf16* as = Abase + (size_t)row * 2048 + ck * 64 + seg * 8;
        const bf16* bs = Bbase + (size_t)row * 2048 + ck * 64 + seg * 8;
        bf16* d = st + row * XP + seg * 8;
        cpa16(d,            as);
        cpa16(d + XBUF,     as + 1024);
        cpa16(d + 2*XBUF,   bs);
        cpa16(d + 3*XBUF,   bs + 1024);
    }
}

__global__ __launch_bounds__(256) void xgemm(int layer) {
    extern __shared__ __align__(16) bf16 xs[];
    const bf16* W     = layer ? g_wih1 : g_wih0;
    const float* bias = layer ? g_bias1 : g_bias0;

    const int tid  = threadIdx.x;
    const int warp = tid >> 5, lane = tid & 31;
    const int wm = warp & 3, wn = warp >> 2;
    const int mB = blockIdx.y, nB = blockIdx.x;
    const bf16* Abase = g_ax + (size_t)(mB * 128) * 2048;
    const bf16* Bbase = W    + (size_t)(nB * 128) * 2048;

    float acc[2][8][4] = {};

    const int arb = (lane & 7) + ((lane >> 3) & 1) * 8;
    const int ac  = (lane >> 4) * 8;
    const int brb = (lane & 7) + ((lane >> 4) & 1) * 8;
    const int bc  = ((lane >> 3) & 1) * 8;

    xload(xs, Abase, Bbase, 0, tid); CPCOMMIT();

    for (int ck = 0; ck < 16; ck++) {
        const int s = ck & 1;
        if (ck + 1 < 16) { xload(xs + (s ^ 1) * XSTAGE, Abase, Bbase, ck + 1, tid); CPCOMMIT(); CPWAIT(1); }
        else             { CPWAIT(0); }
        __syncthreads();

        bf16* Ah = xs + s * XSTAGE;
        bf16* Al = Ah + XBUF;
        bf16* Bh = Al + XBUF;
        bf16* Bl = Bh + XBUF;

        #pragma unroll
        for (int k4 = 0; k4 < 4; k4++) {
            const int co = k4 * 16;
            unsigned aF[2][2][4];
            #pragma unroll
            for (int mb = 0; mb < 2; mb++) {
                int r = wm * 32 + mb * 16 + arb;
                ldsm4(aF[mb][0], Ah + r * XP + co + ac);
                ldsm4(aF[mb][1], Al + r * XP + co + ac);
            }
            unsigned bF[8][2][2];
            #pragma unroll
            for (int p = 0; p < 4; p++) {
                int r = wn * 64 + p * 16 + brb;
                unsigned t[4];
                ldsm4(t, Bh + r * XP + co + bc);
                bF[2*p][0][0]=t[0]; bF[2*p][0][1]=t[1]; bF[2*p+1][0][0]=t[2]; bF[2*p+1][0][1]=t[3];
                ldsm4(t, Bl + r * XP + co + bc);
                bF[2*p][1][0]=t[0]; bF[2*p][1][1]=t[1]; bF[2*p+1][1][0]=t[2]; bF[2*p+1][1][1]=t[3];
            }
            #pragma unroll
            for (int mb = 0; mb < 2; mb++)
                #pragma unroll
                for (int nb = 0; nb < 8; nb++) {
                    mma_bf16(acc[mb][nb], aF[mb][0], bF[nb][0]);  // hi*hi
                    mma_bf16(acc[mb][nb], aF[mb][0], bF[nb][1]);  // hi*lo
                    mma_bf16(acc[mb][nb], aF[mb][1], bF[nb][0]);  // lo*hi
                }
        }
        __syncthreads();
    }

    #pragma unroll
    for (int mb = 0; mb < 2; mb++) {
        int r0 = mB * 128 + wm * 32 + mb * 16 + (lane >> 2);
        #pragma unroll
        for (int nb = 0; nb < 8; nb++) {
            int c0 = nB * 128 + wn * 64 + nb * 8 + 2 * (lane & 3);
            float b0 = bias[c0], b1 = bias[c0 + 1];
            size_t o0 = (size_t)r0 * GG + c0;
            size_t o1 = (size_t)(r0 + 8) * GG + c0;
            g_gx[o0]     = acc[mb][nb][0] + b0;
            g_gx[o0 + 1] = acc[mb][nb][1] + b1;
            g_gx[o1]     = acc[mb][nb][2] + b0;
            g_gx[o1 + 1] = acc[mb][nb][3] + b1;
        }
    }
}

// ---------------- persistent recurrence ----------------
// 128 CTAs x 256 thr. CTA ch owns h-cols [ch*8, ch*8+8) -> 32 gate rows in SMEM.
// h in g_hf fragment layout v2: ld.cg.v4 per kt (L1 bypass -> no acquire fence needed).
#define WPITCH 1032
__global__ __launch_bounds__(256, 1) void recur(int layer, float* __restrict__ lastout) {
    extern __shared__ __align__(16) unsigned char sm[];
    bf16* sWh = (bf16*)sm;                          // [32][WPITCH] hi
    bf16* sWl = (bf16*)(sm + 32 * WPITCH * 2);      // [32][WPITCH] lo
    float* gs = (float*)(sm + 64 * WPITCH * 2);     // [64][33]
    __shared__ unsigned sbase;

    const int tid  = threadIdx.x;
    const int warp = tid >> 5, lane = tid & 31;
    const int wm = warp & 3, wn = warp >> 2;
    const int ch = blockIdx.x;
    const int j0 = ch * 8;
    const bf16* W = layer ? g_whh1 : g_whh0;

    for (int idx = tid; idx < 32 * 128; idx += 256) {
        int n = idx >> 7, u = idx & 127;
        int g = (n >> 3) * 1024 + j0 + (n & 7);
        *(uint4*)(sWh + n * WPITCH + u * 8) = *(const uint4*)(W + (size_t)g * 2048 + u * 8);
        *(uint4*)(sWl + n * WPITCH + u * 8) = *(const uint4*)(W + (size_t)g * 2048 + 1024 + u * 8);
    }
    if (tid == 0) sbase = g_flags[ch];
    __syncthreads();
    const unsigned base = sbase;

    // consumer (GEMM) indices
    const int coff = wm * 8192 + lane * 4;
    const int brow = wn * 16 + (lane & 7) + ((lane >> 4) & 1) * 8;
    const int bcc  = ((lane >> 3) & 1) * 8;
    const bf16* sWh_l = sWh + brow * WPITCH + bcc;
    const bf16* sWl_l = sWl + brow * WPITCH + bcc;

    // writer (elementwise) indices: thread -> (b, col, col+1)
    const int b  = tid >> 2;
    const int jp = tid & 3;
    const int col = j0 + 2 * jp;
    // v2: idx = (b>>4)*8192 + (col>>4)*128 + lane'*4 + reg,
    //     lane' = ((b&7)<<2)|((col>>1)&3), reg = ((col>>3)&1)*2 + ((b>>3)&1)
    const int widx = (b >> 4) * 8192 + (col >> 4) * 128
                   + ((((b & 7) << 2) | ((col >> 1) & 3)) << 2)
                   + ((col >> 3) & 1) * 2 + ((b >> 3) & 1);

    float c0 = 0.0f, c1 = 0.0f;   // cell state (2 cells/thread)

    for (int t = 0; t < TT; t++) {
        const float* gx = g_gx + ((size_t)t * 64 + b) * GG + col;
        float2 gx0 = *(const float2*)(gx);
        float2 gx1 = *(const float2*)(gx + 1024);
        float2 gx2 = *(const float2*)(gx + 2048);
        float2 gx3 = *(const float2*)(gx + 3072);

        float accHH[2][4] = {}, accHL[2][4] = {}, accLH[2][4] = {};
        if (t > 0) {
            const unsigned* hf = g_hf[(t & 1) ^ 1] + coff;
            #pragma unroll 4
            for (int kt = 0; kt < 64; kt++) {
                unsigned aH[4], aL[4], bH[4], bL[4];
                ldg_cg4(aH, hf + kt * 128);
                ldg_cg4(aL, hf + kt * 128 + 32768);
                ldsm4(bH, sWh_l + kt * 16);
                ldsm4(bL, sWl_l + kt * 16);
                unsigned b0h[2] = {bH[0], bH[1]}, b1h[2] = {bH[2], bH[3]};
                unsigned b0l[2] = {bL[0], bL[1]}, b1l[2] = {bL[2], bL[3]};
                mma_bf16(accHH[0], aH, b0h);
                mma_bf16(accHL[0], aH, b0l);
                mma_bf16(accLH[0], aL, b0h);
                mma_bf16(accHH[1], aH, b1h);
                mma_bf16(accHL[1], aH, b1l);
                mma_bf16(accLH[1], aL, b1h);
            }
        }

        // stage gate accumulators to smem [64][33]
        {
            int r = wm * 16 + (lane >> 2);
            #pragma unroll
            for (int nb = 0; nb < 2; nb++) {
                int c = wn * 16 + nb * 8 + 2 * (lane & 3);
                gs[r * 33 + c]           = accHH[nb][0] + accHL[nb][0] + accLH[nb][0];
                gs[r * 33 + c + 1]       = accHH[nb][1] + accHL[nb][1] + accLH[nb][1];
                gs[(r + 8) * 33 + c]     = accHH[nb][2] + accHL[nb][2] + accLH[nb][2];
                gs[(r + 8) * 33 + c + 1] = accHH[nb][3] + accHL[nb][3] + accLH[nb][3];
            }
        }
        __syncthreads();

        // LSTM elementwise: 2 cells per thread (cols col, col+1)
        {
            float gi0 = gs[b * 33 + 2*jp]          + gx0.x;
            float gi1 = gs[b * 33 + 2*jp + 1]      + gx0.y;
            float gf0 = gs[b * 33 + 8 + 2*jp]      + gx1.x;
            float gf1 = gs[b * 33 + 8 + 2*jp + 1]  + gx1.y;
            float gg0 = gs[b * 33 + 16 + 2*jp]     + gx2.x;
            float gg1 = gs[b * 33 + 16 + 2*jp + 1] + gx2.y;
            float go0 = gs[b * 33 + 24 + 2*jp]     + gx3.x;
            float go1 = gs[b * 33 + 24 + 2*jp + 1] + gx3.y;

            float i0 = sigf(gi0), f0 = sigf(gf0), G0 = tanhf(gg0), o0 = sigf(go0);
            float i1 = sigf(gi1), f1 = sigf(gf1), G1 = tanhf(gg1), o1 = sigf(go1);
            c0 = f0 * c0 + i0 * G0;
            c1 = f1 * c1 + i1 * G1;
            float hn0 = o0 * tanhf(c0);
            float hn1 = o1 * tanhf(c1);

            bf16 h0h = __float2bfloat16(hn0);
            bf16 h1h = __float2bfloat16(hn1);
            unsigned hiw = pack2(h0h, h1h);
            unsigned low = pack2(__float2bfloat16(hn0 - __bfloat162float(h0h)),
                                 __float2bfloat16(hn1 - __bfloat162float(h1h)));
            unsigned* dst = (unsigned*)g_hf[t & 1];
            dst[widx]         = hiw;
            dst[widx + 32768] = low;
            if (layer == 0) {
                bf16* ax = g_ax + ((size_t)t * 64 + b) * 2048 + col;
                *(unsigned*)ax          = hiw;
                *(unsigned*)(ax + 1024) = low;
            } else if (t == TT - 1) {
                lastout[b * HH + col]     = hn0;
                lastout[b * HH + col + 1] = hn1;
            }
        }

        // release: all threads' h stores ordered before flag; then hot-spin barrier.
        __threadfence();
        __syncthreads();
        const unsigned target = base + (unsigned)t + 1u;
        if (tid == 0) st_rel(&g_flags[ch], target);
        if (tid < 128) {
            while ((int)(ld_acq(&g_flags[tid]) - target) < 0) { }
        }
        __syncthreads();
        // no acquire fence needed: h reads use ld.cg (L2 is the coherence point)
    }
}

// ---------------- host launcher ----------------
extern "C" void kernel_launch(void* const* d_in, const int* in_sizes, int n_in,
                              void* d_out, int out_size) {
    (void)in_sizes; (void)n_in; (void)out_size;
    const float* x     = (const float*)d_in[0];
    const float* w_ih0 = (const float*)d_in[1];
    const float* w_hh0 = (const float*)d_in[2];
    const float* b_ih0 = (const float*)d_in[3];
    const float* b_hh0 = (const float*)d_in[4];
    const float* w_ih1 = (const float*)d_in[5];
    const float* w_hh1 = (const float*)d_in[6];
    const float* b_ih1 = (const float*)d_in[7];
    const float* b_hh1 = (const float*)d_in[8];
    const unsigned* m_ih0 = (const unsigned*)d_in[9];
    const unsigned* m_hh0 = (const unsigned*)d_in[10];
    const unsigned* m_ih1 = (const unsigned*)d_in[11];
    const unsigned* m_hh1 = (const unsigned*)d_in[12];
    float* out = (float*)d_out;

    const int recurSmem = 64 * WPITCH * 2 + 64 * 33 * 4;   // 140544
    cudaFuncSetAttribute(recur, cudaFuncAttributeMaxDynamicSharedMemorySize, recurSmem);
    cudaFuncSetAttribute(xgemm, cudaFuncAttributeMaxDynamicSharedMemorySize, XSMEM);

    prep_all<<<65537, 256>>>(w_ih0, m_ih0, w_hh0, m_hh0, w_ih1, m_ih1, w_hh1, m_hh1,
                             b_ih0, b_hh0, b_ih1, b_hh1);
    prep_ax<<<MTOT / 2, 256>>>(x);

    dim3 gemmGrid(GG / 128, MTOT / 128);   // (32, 256)

    xgemm<<<gemmGrid, 256, XSMEM>>>(0);
    recur<<<128, 256, recurSmem>>>(0, nullptr);   // also writes g_ax for layer 1

    xgemm<<<gemmGrid, 256, XSMEM>>>(1);
    recur<<<128, 256, recurSmem>>>(1, out);
}

// round 9
// speedup vs baseline: 1.5803x; 1.1135x over previous
#include <cuda_runtime.h>
#include <cuda_bf16.h>
#include <cstdint>

typedef __nv_bfloat16 bf16;

#define BSZ 64
#define TT  512
#define FF  1024
#define HH  1024
#define GG  4096
#define KK  1024
#define MTOT (TT*BSZ)   // 32768

// ---------------- device scratch ----------------
__device__ __align__(16) bf16  g_wih0[GG * 2 * KK];   // [G][hi(0:K) | lo(K:2K)]
__device__ __align__(16) bf16  g_whh0[GG * 2 * KK];
__device__ __align__(16) bf16  g_wih1[GG * 2 * KK];
__device__ __align__(16) bf16  g_whh1[GG * 2 * KK];
__device__ __align__(16) float g_bias0[GG];
__device__ __align__(16) float g_bias1[GG];
__device__ __align__(16) float g_gx[(size_t)MTOT * GG];     // gates_x (512 MB)
__device__ __align__(16) bf16  g_ax[(size_t)MTOT * 2 * KK]; // split A for xgemm (128 MB)
// h in mma-fragment layout v2:
//   u32 idx(hiLo, wm, kt, lane, reg) = hiLo*32768 + wm*8192 + kt*128 + lane*4 + reg
__device__ __align__(16) unsigned g_hf[2][65536];

// grid-barrier flags: monotonic, never reset (deterministic across graph replays)
__device__ volatile unsigned g_flags[128];

// ---------------- helpers ----------------
__device__ __forceinline__ unsigned pack2(bf16 a, bf16 b) {
    return (unsigned)__bfloat16_as_ushort(a) | ((unsigned)__bfloat16_as_ushort(b) << 16);
}

// exact split v = hi + r, lo = bf16(r)
__device__ __forceinline__ void split2(float a, float b, unsigned &h, unsigned &l) {
    bf16 ha = __float2bfloat16(a);
    bf16 hb = __float2bfloat16(b);
    bf16 la = __float2bfloat16(a - __bfloat162float(ha));
    bf16 lb = __float2bfloat16(b - __bfloat162float(hb));
    h = pack2(ha, hb);
    l = pack2(la, lb);
}

__device__ __forceinline__ void mma_bf16(float acc[4], const unsigned a[4], const unsigned b[2]) {
    asm volatile(
        "mma.sync.aligned.m16n8k16.row.col.f32.bf16.bf16.f32 "
        "{%0,%1,%2,%3},{%4,%5,%6,%7},{%8,%9},{%0,%1,%2,%3};\n"
        : "+f"(acc[0]), "+f"(acc[1]), "+f"(acc[2]), "+f"(acc[3])
        : "r"(a[0]), "r"(a[1]), "r"(a[2]), "r"(a[3]), "r"(b[0]), "r"(b[1]));
}

__device__ __forceinline__ void ldsm4(unsigned r[4], const void* p) {
    unsigned addr = (unsigned)__cvta_generic_to_shared(p);
    asm volatile("ldmatrix.sync.aligned.m8n8.x4.shared.b16 {%0,%1,%2,%3},[%4];\n"
                 : "=r"(r[0]), "=r"(r[1]), "=r"(r[2]), "=r"(r[3]) : "r"(addr));
}

// L1-bypass vector load (h ping-pong: L2 is the coherence point)
__device__ __forceinline__ void ldg_cg4(unsigned r[4], const void* p) {
    asm volatile("ld.global.cg.v4.u32 {%0,%1,%2,%3}, [%4];\n"
                 : "=r"(r[0]), "=r"(r[1]), "=r"(r[2]), "=r"(r[3]) : "l"(p));
}

__device__ __forceinline__ void st_rel(volatile unsigned* p, unsigned v) {
    asm volatile("st.release.gpu.global.u32 [%0], %1;\n" :: "l"((void*)p), "r"(v) : "memory");
}
__device__ __forceinline__ unsigned ld_acq(volatile unsigned* p) {
    unsigned v;
    asm volatile("ld.acquire.gpu.global.u32 %0, [%1];\n" : "=r"(v) : "l"((void*)p) : "memory");
    return v;
}

__device__ __forceinline__ void cpa16(void* dst, const void* src) {
    unsigned d = (unsigned)__cvta_generic_to_shared(dst);
    asm volatile("cp.async.cg.shared.global [%0], [%1], 16;\n" :: "r"(d), "l"(src));
}
#define CPCOMMIT() asm volatile("cp.async.commit_group;\n")
#define CPWAIT(n)  asm volatile("cp.async.wait_group %0;\n" :: "n"(n))

__device__ __forceinline__ float sigf(float x) { return 1.0f / (1.0f + expf(-x)); }

// ---------------- prep: all weights + biases in ONE launch ----------------
__global__ void prep_all(const float* __restrict__ w0, const unsigned* __restrict__ m0,
                         const float* __restrict__ w1, const unsigned* __restrict__ m1,
                         const float* __restrict__ w2, const unsigned* __restrict__ m2,
                         const float* __restrict__ w3, const unsigned* __restrict__ m3,
                         const float* __restrict__ bi0, const float* __restrict__ bh0,
                         const float* __restrict__ bi1, const float* __restrict__ bh1) {
    int blk = blockIdx.x;
    if (blk < 65536) {
        int which = blk >> 14;
        int idx = (blk & 16383) * 256 + threadIdx.x;
        const float*    w = (which == 0) ? w0 : (which == 1) ? w1 : (which == 2) ? w2 : w3;
        const unsigned* m = (which == 0) ? m0 : (which == 1) ? m1 : (which == 2) ? m2 : m3;
        bf16* dst = (which == 0) ? g_wih0 : (which == 1) ? g_whh0 : (which == 2) ? g_wih1 : g_whh1;
        int g = idx >> 10, k = idx & 1023;
        float v = (m[idx] != 0u) ? w[idx] : 0.0f;
        bf16 hi = __float2bfloat16(v);
        float r = v - __bfloat162float(hi);
        dst[(size_t)g * 2048 + k]        = hi;
        dst[(size_t)g * 2048 + 1024 + k] = __float2bfloat16(r);
    } else {
        for (int i = threadIdx.x; i < GG; i += 256) {
            g_bias0[i] = bi0[i] + bh0[i];
            g_bias1[i] = bi1[i] + bh1[i];
        }
    }
}

// ---------------- prep: x -> g_ax split rows (m = t*64 + b) ----------------
__global__ void prep_ax(const float* __restrict__ x) {
    int m = blockIdx.x * 2 + (threadIdx.x >> 7);
    int c = (threadIdx.x & 127) * 8;
    const float* src = x + ((size_t)(m & 63) * TT + (m >> 6)) * FF + c;
    float4 v0 = *(const float4*)src;
    float4 v1 = *(const float4*)(src + 4);
    unsigned h0, h1, h2, h3, l0, l1, l2, l3;
    split2(v0.x, v0.y, h0, l0); split2(v0.z, v0.w, h1, l1);
    split2(v1.x, v1.y, h2, l2); split2(v1.z, v1.w, h3, l3);
    bf16* d = g_ax + (size_t)m * 2048 + c;
    *(uint4*)d          = make_uint4(h0, h1, h2, h3);
    *(uint4*)(d + 1024) = make_uint4(l0, l1, l2, l3);
}

// ---------------- big input GEMM: gates_x = A @ W^T + bias ----------------
#define XP 72                 // smem row pitch (bf16)
#define XBUF (128 * XP)       // one buffer (elems)
#define XSTAGE (4 * XBUF)     // Ah,Al,Bh,Bl
#define XSMEM (2 * XSTAGE * 2)  // bytes = 147456

__device__ __forceinline__ void xload(bf16* st, const bf16* Abase, const bf16* Bbase,
                                      int ck, int tid) {
    #pragma unroll
    for (int i = 0; i < 4; i++) {
        int j = tid + i * 256;                 // [0,1024)
        int row = j >> 3, seg = j & 7;
        const bf16* as = Abase + (size_t)row * 2048 + ck * 64 + seg * 8;
        const bf16* bs = Bbase + (size_t)row * 2048 + ck * 64 + seg * 8;
        bf16* d = st + row * XP + seg * 8;
        cpa16(d,            as);
        cpa16(d + XBUF,     as + 1024);
        cpa16(d + 2*XBUF,   bs);
        cpa16(d + 3*XBUF,   bs + 1024);
    }
}

__global__ __launch_bounds__(256) void xgemm(int layer) {
    extern __shared__ __align__(16) bf16 xs[];
    const bf16* W     = layer ? g_wih1 : g_wih0;
    const float* bias = layer ? g_bias1 : g_bias0;

    const int tid  = threadIdx.x;
    const int warp = tid >> 5, lane = tid & 31;
    const int wm = warp & 3, wn = warp >> 2;
    const int mB = blockIdx.y, nB = blockIdx.x;
    const bf16* Abase = g_ax + (size_t)(mB * 128) * 2048;
    const bf16* Bbase = W    + (size_t)(nB * 128) * 2048;

    float acc[2][8][4] = {};

    const int arb = (lane & 7) + ((lane >> 3) & 1) * 8;
    const int ac  = (lane >> 4) * 8;
    const int brb = (lane & 7) + ((lane >> 4) & 1) * 8;
    const int bc  = ((lane >> 3) & 1) * 8;

    xload(xs, Abase, Bbase, 0, tid); CPCOMMIT();

    for (int ck = 0; ck < 16; ck++) {
        const int s = ck & 1;
        if (ck + 1 < 16) { xload(xs + (s ^ 1) * XSTAGE, Abase, Bbase, ck + 1, tid); CPCOMMIT(); CPWAIT(1); }
        else             { CPWAIT(0); }
        __syncthreads();

        bf16* Ah = xs + s * XSTAGE;
        bf16* Al = Ah + XBUF;
        bf16* Bh = Al + XBUF;
        bf16* Bl = Bh + XBUF;

        #pragma unroll
        for (int k4 = 0; k4 < 4; k4++) {
            const int co = k4 * 16;
            unsigned aF[2][2][4];
            #pragma unroll
            for (int mb = 0; mb < 2; mb++) {
                int r = wm * 32 + mb * 16 + arb;
                ldsm4(aF[mb][0], Ah + r * XP + co + ac);
                ldsm4(aF[mb][1], Al + r * XP + co + ac);
            }
            unsigned bF[8][2][2];
            #pragma unroll
            for (int p = 0; p < 4; p++) {
                int r = wn * 64 + p * 16 + brb;
                unsigned t[4];
                ldsm4(t, Bh + r * XP + co + bc);
                bF[2*p][0][0]=t[0]; bF[2*p][0][1]=t[1]; bF[2*p+1][0][0]=t[2]; bF[2*p+1][0][1]=t[3];
                ldsm4(t, Bl + r * XP + co + bc);
                bF[2*p][1][0]=t[0]; bF[2*p][1][1]=t[1]; bF[2*p+1][1][0]=t[2]; bF[2*p+1][1][1]=t[3];
            }
            #pragma unroll
            for (int mb = 0; mb < 2; mb++)
                #pragma unroll
                for (int nb = 0; nb < 8; nb++) {
                    mma_bf16(acc[mb][nb], aF[mb][0], bF[nb][0]);  // hi*hi
                    mma_bf16(acc[mb][nb], aF[mb][0], bF[nb][1]);  // hi*lo
                    mma_bf16(acc[mb][nb], aF[mb][1], bF[nb][0]);  // lo*hi
                }
        }
        __syncthreads();
    }

    #pragma unroll
    for (int mb = 0; mb < 2; mb++) {
        int r0 = mB * 128 + wm * 32 + mb * 16 + (lane >> 2);
        #pragma unroll
        for (int nb = 0; nb < 8; nb++) {
            int c0 = nB * 128 + wn * 64 + nb * 8 + 2 * (lane & 3);
            float b0 = bias[c0], b1 = bias[c0 + 1];
            size_t o0 = (size_t)r0 * GG + c0;
            size_t o1 = (size_t)(r0 + 8) * GG + c0;
            g_gx[o0]     = acc[mb][nb][0] + b0;
            g_gx[o0 + 1] = acc[mb][nb][1] + b1;
            g_gx[o1]     = acc[mb][nb][2] + b0;
            g_gx[o1 + 1] = acc[mb][nb][3] + b1;
        }
    }
}

// ---------------- persistent recurrence (512 threads, split-K x2) ----------------
// 128 CTAs x 512 thr. CTA ch owns h-cols [ch*8, ch*8+8) -> 32 gate rows in SMEM.
// 16 warps: wm = warp&3 (batch row block), wn = (warp>>2)&1 (gate 16-col block),
// wk = warp>>3 (K half). Partial sums staged per-K-half in smem, summed in elementwise.
#define WPITCH 1032
#define GSF    2112   // 64*33 floats per staging buffer
#define RSMEM  (64 * WPITCH * 2 + 2 * GSF * 4)   // 132096 + 16896 = 148992
__global__ __launch_bounds__(512, 1) void recur(int layer, float* __restrict__ lastout) {
    extern __shared__ __align__(16) unsigned char sm[];
    bf16* sWh = (bf16*)sm;                          // [32][WPITCH] hi
    bf16* sWl = (bf16*)(sm + 32 * WPITCH * 2);      // [32][WPITCH] lo
    float* gs = (float*)(sm + 64 * WPITCH * 2);     // [2][64][33]
    __shared__ unsigned sbase;

    const int tid  = threadIdx.x;
    const int warp = tid >> 5, lane = tid & 31;
    const int wm = warp & 3, wn = (warp >> 2) & 1, wk = warp >> 3;
    const int ch = blockIdx.x;
    const int j0 = ch * 8;
    const bf16* W = layer ? g_whh1 : g_whh0;

    for (int idx = tid; idx < 32 * 128; idx += 512) {
        int n = idx >> 7, u = idx & 127;
        int g = (n >> 3) * 1024 + j0 + (n & 7);
        *(uint4*)(sWh + n * WPITCH + u * 8) = *(const uint4*)(W + (size_t)g * 2048 + u * 8);
        *(uint4*)(sWl + n * WPITCH + u * 8) = *(const uint4*)(W + (size_t)g * 2048 + 1024 + u * 8);
    }
    if (tid == 0) sbase = g_flags[ch];
    __syncthreads();
    const unsigned base = sbase;

    // consumer (GEMM) indices
    const int coff = wm * 8192 + lane * 4;
    const int brow = wn * 16 + (lane & 7) + ((lane >> 4) & 1) * 8;
    const int bcc  = ((lane >> 3) & 1) * 8;
    const bf16* sWh_l = sWh + brow * WPITCH + bcc;
    const bf16* sWl_l = sWl + brow * WPITCH + bcc;
    float* gw = gs + wk * GSF;

    // writer (elementwise) indices: threads 0-255, each -> (b, col, col+1)
    const int b  = (tid & 255) >> 2;
    const int jp = tid & 3;
    const int col = j0 + 2 * jp;
    const int widx = (b >> 4) * 8192 + (col >> 4) * 128
                   + ((((b & 7) << 2) | ((col >> 1) & 3)) << 2)
                   + ((col >> 3) & 1) * 2 + ((b >> 3) & 1);

    float c0 = 0.0f, c1 = 0.0f;   // cell state (threads 0-255 only)

    for (int t = 0; t < TT; t++) {
        float2 gx0, gx1, gx2, gx3;
        if (tid < 256) {
            const float* gx = g_gx + ((size_t)t * 64 + b) * GG + col;
            gx0 = *(const float2*)(gx);
            gx1 = *(const float2*)(gx + 1024);
            gx2 = *(const float2*)(gx + 2048);
            gx3 = *(const float2*)(gx + 3072);
        }

        float accHH[2][4] = {}, accHL[2][4] = {}, accLH[2][4] = {};
        if (t > 0) {
            const unsigned* hf = g_hf[(t & 1) ^ 1] + coff + wk * 32 * 128;
            #pragma unroll 4
            for (int k = 0; k < 32; k++) {
                unsigned aH[4], aL[4], bH[4], bL[4];
                ldg_cg4(aH, hf + k * 128);
                ldg_cg4(aL, hf + k * 128 + 32768);
                ldsm4(bH, sWh_l + (wk * 32 + k) * 16);
                ldsm4(bL, sWl_l + (wk * 32 + k) * 16);
                unsigned b0h[2] = {bH[0], bH[1]}, b1h[2] = {bH[2], bH[3]};
                unsigned b0l[2] = {bL[0], bL[1]}, b1l[2] = {bL[2], bL[3]};
                mma_bf16(accHH[0], aH, b0h);
                mma_bf16(accHL[0], aH, b0l);
                mma_bf16(accLH[0], aL, b0h);
                mma_bf16(accHH[1], aH, b1h);
                mma_bf16(accHL[1], aH, b1l);
                mma_bf16(accLH[1], aL, b1h);
            }
        }

        // stage gate partial sums to this K-half's smem buffer [64][33]
        {
            int r = wm * 16 + (lane >> 2);
            #pragma unroll
            for (int nb = 0; nb < 2; nb++) {
                int c = wn * 16 + nb * 8 + 2 * (lane & 3);
                gw[r * 33 + c]           = accHH[nb][0] + accHL[nb][0] + accLH[nb][0];
                gw[r * 33 + c + 1]       = accHH[nb][1] + accHL[nb][1] + accLH[nb][1];
                gw[(r + 8) * 33 + c]     = accHH[nb][2] + accHL[nb][2] + accLH[nb][2];
                gw[(r + 8) * 33 + c + 1] = accHH[nb][3] + accHL[nb][3] + accLH[nb][3];
            }
        }
        __syncthreads();

        // LSTM elementwise: threads 0-255, 2 cells each (cols col, col+1)
        if (tid < 256) {
            float gi0 = gs[b * 33 + 2*jp]          + gs[GSF + b * 33 + 2*jp]          + gx0.x;
            float gi1 = gs[b * 33 + 2*jp + 1]      + gs[GSF + b * 33 + 2*jp + 1]      + gx0.y;
            float gf0 = gs[b * 33 + 8 + 2*jp]      + gs[GSF + b * 33 + 8 + 2*jp]      + gx1.x;
            float gf1 = gs[b * 33 + 8 + 2*jp + 1]  + gs[GSF + b * 33 + 8 + 2*jp + 1]  + gx1.y;
            float gg0 = gs[b * 33 + 16 + 2*jp]     + gs[GSF + b * 33 + 16 + 2*jp]     + gx2.x;
            float gg1 = gs[b * 33 + 16 + 2*jp + 1] + gs[GSF + b * 33 + 16 + 2*jp + 1] + gx2.y;
            float go0 = gs[b * 33 + 24 + 2*jp]     + gs[GSF + b * 33 + 24 + 2*jp]     + gx3.x;
            float go1 = gs[b * 33 + 24 + 2*jp + 1] + gs[GSF + b * 33 + 24 + 2*jp + 1] + gx3.y;

            float i0 = sigf(gi0), f0 = sigf(gf0), G0 = tanhf(gg0), o0 = sigf(go0);
            float i1 = sigf(gi1), f1 = sigf(gf1), G1 = tanhf(gg1), o1 = sigf(go1);
            c0 = f0 * c0 + i0 * G0;
            c1 = f1 * c1 + i1 * G1;
            float hn0 = o0 * tanhf(c0);
            float hn1 = o1 * tanhf(c1);

            bf16 h0h = __float2bfloat16(hn0);
            bf16 h1h = __float2bfloat16(hn1);
            unsigned hiw = pack2(h0h, h1h);
            unsigned low = pack2(__float2bfloat16(hn0 - __bfloat162float(h0h)),
                                 __float2bfloat16(hn1 - __bfloat162float(h1h)));
            unsigned* dst = (unsigned*)g_hf[t & 1];
            dst[widx]         = hiw;
            dst[widx + 32768] = low;
            if (layer == 0) {
                bf16* ax = g_ax + ((size_t)t * 64 + b) * 2048 + col;
                *(unsigned*)ax          = hiw;
                *(unsigned*)(ax + 1024) = low;
            } else if (t == TT - 1) {
                lastout[b * HH + col]     = hn0;
                lastout[b * HH + col + 1] = hn1;
            }
        }

        // release: all threads' h stores ordered before flag; then hot-spin barrier.
        __threadfence();
        __syncthreads();
        const unsigned target = base + (unsigned)t + 1u;
        if (tid == 0) st_rel(&g_flags[ch], target);
        if (tid < 128) {
            while ((int)(ld_acq(&g_flags[tid]) - target) < 0) { }
        }
        __syncthreads();
        // no acquire fence needed: h reads use ld.cg (L2 is the coherence point)
    }
}

// ---------------- host launcher ----------------
extern "C" void kernel_launch(void* const* d_in, const int* in_sizes, int n_in,
                              void* d_out, int out_size) {
    (void)in_sizes; (void)n_in; (void)out_size;
    const float* x     = (const float*)d_in[0];
    const float* w_ih0 = (const float*)d_in[1];
    const float* w_hh0 = (const float*)d_in[2];
    const float* b_ih0 = (const float*)d_in[3];
    const float* b_hh0 = (const float*)d_in[4];
    const float* w_ih1 = (const float*)d_in[5];
    const float* w_hh1 = (const float*)d_in[6];
    const float* b_ih1 = (const float*)d_in[7];
    const float* b_hh1 = (const float*)d_in[8];
    const unsigned* m_ih0 = (const unsigned*)d_in[9];
    const unsigned* m_hh0 = (const unsigned*)d_in[10];
    const unsigned* m_ih1 = (const unsigned*)d_in[11];
    const unsigned* m_hh1 = (const unsigned*)d_in[12];
    float* out = (float*)d_out;

    cudaFuncSetAttribute(recur, cudaFuncAttributeMaxDynamicSharedMemorySize, RSMEM);
    cudaFuncSetAttribute(xgemm, cudaFuncAttributeMaxDynamicSharedMemorySize, XSMEM);

    prep_all<<<65537, 256>>>(w_ih0, m_ih0, w_hh0, m_hh0, w_ih1, m_ih1, w_hh1, m_hh1,
                             b_ih0, b_hh0, b_ih1, b_hh1);
    prep_ax<<<MTOT / 2, 256>>>(x);

    dim3 gemmGrid(GG / 128, MTOT / 128);   // (32, 256)

    xgemm<<<gemmGrid, 256, XSMEM>>>(0);
    recur<<<128, 512, RSMEM>>>(0, nullptr);   // also writes g_ax for layer 1

    xgemm<<<gemmGrid, 256, XSMEM>>>(1);
    recur<<<128, 512, RSMEM>>>(1, out);
}

// round 10
// speedup vs baseline: 1.9066x; 1.2064x over previous
#include <cuda_runtime.h>
#include <cuda_bf16.h>
#include <cuda_fp16.h>
#include <cstdint>

typedef __nv_bfloat16 bf16;

#define BSZ 64
#define TT  512
#define FF  1024
#define HH  1024
#define GG  4096
#define KK  1024
#define MTOT (TT*BSZ)   // 32768

// ---------------- device scratch ----------------
__device__ __align__(16) bf16   g_wih0[GG * 2 * KK];   // [G][hi | lo] bf16 (xgemm)
__device__ __align__(16) bf16   g_wih1[GG * 2 * KK];
__device__ __align__(16) __half g_whh0[GG * 2 * KK];   // [G][hi | lo*1024] fp16 (recur)
__device__ __align__(16) __half g_whh1[GG * 2 * KK];
__device__ __align__(16) float  g_bias0[GG];
__device__ __align__(16) float  g_bias1[GG];
__device__ __align__(16) float  g_gx[(size_t)MTOT * GG];     // gates_x (512 MB)
__device__ __align__(16) bf16   g_ax[(size_t)MTOT * 2 * KK]; // split A for xgemm (128 MB)
// h in mma-fragment layout (fp16x2, single plane):
//   u32 idx(wm, kt, lane, reg) = wm*8192 + kt*128 + lane*4 + reg
__device__ __align__(16) unsigned g_hf[2][32768];

// grid-barrier flags: monotonic, never reset (deterministic across graph replays)
__device__ volatile unsigned g_flags[128];

// ---------------- helpers ----------------
__device__ __forceinline__ unsigned pack2(bf16 a, bf16 b) {
    return (unsigned)__bfloat16_as_ushort(a) | ((unsigned)__bfloat16_as_ushort(b) << 16);
}

// exact split v = hi + r, lo = bf16(r)
__device__ __forceinline__ void split2(float a, float b, unsigned &h, unsigned &l) {
    bf16 ha = __float2bfloat16(a);
    bf16 hb = __float2bfloat16(b);
    bf16 la = __float2bfloat16(a - __bfloat162float(ha));
    bf16 lb = __float2bfloat16(b - __bfloat162float(hb));
    h = pack2(ha, hb);
    l = pack2(la, lb);
}

__device__ __forceinline__ void mma_bf16(float acc[4], const unsigned a[4], const unsigned b[2]) {
    asm volatile(
        "mma.sync.aligned.m16n8k16.row.col.f32.bf16.bf16.f32 "
        "{%0,%1,%2,%3},{%4,%5,%6,%7},{%8,%9},{%0,%1,%2,%3};\n"
        : "+f"(acc[0]), "+f"(acc[1]), "+f"(acc[2]), "+f"(acc[3])
        : "r"(a[0]), "r"(a[1]), "r"(a[2]), "r"(a[3]), "r"(b[0]), "r"(b[1]));
}

__device__ __forceinline__ void mma_f16(float acc[4], const unsigned a[4], unsigned b0, unsigned b1) {
    asm volatile(
        "mma.sync.aligned.m16n8k16.row.col.f32.f16.f16.f32 "
        "{%0,%1,%2,%3},{%4,%5,%6,%7},{%8,%9},{%0,%1,%2,%3};\n"
        : "+f"(acc[0]), "+f"(acc[1]), "+f"(acc[2]), "+f"(acc[3])
        : "r"(a[0]), "r"(a[1]), "r"(a[2]), "r"(a[3]), "r"(b0), "r"(b1));
}

__device__ __forceinline__ void ldsm4(unsigned r[4], const void* p) {
    unsigned addr = (unsigned)__cvta_generic_to_shared(p);
    asm volatile("ldmatrix.sync.aligned.m8n8.x4.shared.b16 {%0,%1,%2,%3},[%4];\n"
                 : "=r"(r[0]), "=r"(r[1]), "=r"(r[2]), "=r"(r[3]) : "r"(addr));
}

// L1-bypass vector load (h ping-pong: L2 is the coherence point)
__device__ __forceinline__ void ldg_cg4(unsigned r[4], const void* p) {
    asm volatile("ld.global.cg.v4.u32 {%0,%1,%2,%3}, [%4];\n"
                 : "=r"(r[0]), "=r"(r[1]), "=r"(r[2]), "=r"(r[3]) : "l"(p));
}

__device__ __forceinline__ void st_rel(volatile unsigned* p, unsigned v) {
    asm volatile("st.release.gpu.global.u32 [%0], %1;\n" :: "l"((void*)p), "r"(v) : "memory");
}
__device__ __forceinline__ unsigned ld_acq(volatile unsigned* p) {
    unsigned v;
    asm volatile("ld.acquire.gpu.global.u32 %0, [%1];\n" : "=r"(v) : "l"((void*)p) : "memory");
    return v;
}

__device__ __forceinline__ void cpa16(void* dst, const void* src) {
    unsigned d = (unsigned)__cvta_generic_to_shared(dst);
    asm volatile("cp.async.cg.shared.global [%0], [%1], 16;\n" :: "r"(d), "l"(src));
}
#define CPCOMMIT() asm volatile("cp.async.commit_group;\n")
#define CPWAIT(n)  asm volatile("cp.async.wait_group %0;\n" :: "n"(n))

__device__ __forceinline__ float sigf(float x) { return 1.0f / (1.0f + expf(-x)); }

// ---------------- prep: all weights + biases in ONE launch ----------------
// wih -> bf16 hi/lo split; whh -> fp16 hi + (lo*1024) fp16. Masks are 32-bit words.
__global__ void prep_all(const float* __restrict__ w0, const unsigned* __restrict__ m0,
                         const float* __restrict__ w1, const unsigned* __restrict__ m1,
                         const float* __restrict__ w2, const unsigned* __restrict__ m2,
                         const float* __restrict__ w3, const unsigned* __restrict__ m3,
                         const float* __restrict__ bi0, const float* __restrict__ bh0,
                         const float* __restrict__ bi1, const float* __restrict__ bh1) {
    int blk = blockIdx.x;
    if (blk < 65536) {
        int which = blk >> 14;
        int idx = (blk & 16383) * 256 + threadIdx.x;
        const float*    w = (which == 0) ? w0 : (which == 1) ? w1 : (which == 2) ? w2 : w3;
        const unsigned* m = (which == 0) ? m0 : (which == 1) ? m1 : (which == 2) ? m2 : m3;
        int g = idx >> 10, k = idx & 1023;
        float v = (m[idx] != 0u) ? w[idx] : 0.0f;
        if (which == 1 || which == 3) {            // whh -> fp16, lo scaled by 1024
            __half* dst = (which == 1) ? g_whh0 : g_whh1;
            __half hi = __float2half_rn(v);
            float r = (v - __half2float(hi)) * 1024.0f;
            dst[(size_t)g * 2048 + k]        = hi;
            dst[(size_t)g * 2048 + 1024 + k] = __float2half_rn(r);
        } else {                                   // wih -> bf16 split
            bf16* dst = (which == 0) ? g_wih0 : g_wih1;
            bf16 hi = __float2bfloat16(v);
            float r = v - __bfloat162float(hi);
            dst[(size_t)g * 2048 + k]        = hi;
            dst[(size_t)g * 2048 + 1024 + k] = __float2bfloat16(r);
        }
    } else {
        for (int i = threadIdx.x; i < GG; i += 256) {
            g_bias0[i] = bi0[i] + bh0[i];
            g_bias1[i] = bi1[i] + bh1[i];
        }
    }
}

// ---------------- prep: x -> g_ax split rows (m = t*64 + b) ----------------
__global__ void prep_ax(const float* __restrict__ x) {
    int m = blockIdx.x * 2 + (threadIdx.x >> 7);
    int c = (threadIdx.x & 127) * 8;
    const float* src = x + ((size_t)(m & 63) * TT + (m >> 6)) * FF + c;
    float4 v0 = *(const float4*)src;
    float4 v1 = *(const float4*)(src + 4);
    unsigned h0, h1, h2, h3, l0, l1, l2, l3;
    split2(v0.x, v0.y, h0, l0); split2(v0.z, v0.w, h1, l1);
    split2(v1.x, v1.y, h2, l2); split2(v1.z, v1.w, h3, l3);
    bf16* d = g_ax + (size_t)m * 2048 + c;
    *(uint4*)d          = make_uint4(h0, h1, h2, h3);
    *(uint4*)(d + 1024) = make_uint4(l0, l1, l2, l3);
}

// ---------------- big input GEMM: gates_x = A @ W^T + bias ----------------
// A = g_ax [32768][2048] split bf16; W split [4096][2048]; C = g_gx fp32.
// CTA tile 128x128, 8 warps 4(m)x2(n), warp tile 32x64.
// K chunks of 64 (128-B rows), cp.async THREE-stage pipeline.
#define XP 72                 // smem row pitch (bf16)
#define XBUF (128 * XP)       // one buffer (elems)
#define XSTAGE (4 * XBUF)     // Ah,Al,Bh,Bl
#define XSMEM (3 * XSTAGE * 2)  // bytes = 221184

__device__ __forceinline__ void xload(bf16* st, const bf16* Abase, const bf16* Bbase,
                                      int ck, int tid) {
    #pragma unroll
    for (int i = 0; i < 4; i++) {
        int j = tid + i * 256;                 // [0,1024)
        int row = j >> 3, seg = j & 7;
        const bf16* as = Abase + (size_t)row * 2048 + ck * 64 + seg * 8;
        const bf16* bs = Bbase + (size_t)row * 2048 + ck * 64 + seg * 8;
        bf16* d = st + row * XP + seg * 8;
        cpa16(d,            as);
        cpa16(d + XBUF,     as + 1024);
        cpa16(d + 2*XBUF,   bs);
        cpa16(d + 3*XBUF,   bs + 1024);
    }
}

__global__ __launch_bounds__(256) void xgemm(int layer) {
    extern __shared__ __align__(16) bf16 xs[];
    const bf16* W     = layer ? g_wih1 : g_wih0;
    const float* bias = layer ? g_bias1 : g_bias0;

    const int tid  = threadIdx.x;
    const int warp = tid >> 5, lane = tid & 31;
    const int wm = warp & 3, wn = warp >> 2;
    const int mB = blockIdx.y, nB = blockIdx.x;
    const bf16* Abase = g_ax + (size_t)(mB * 128) * 2048;
    const bf16* Bbase = W    + (size_t)(nB * 128) * 2048;

    float acc[2][8][4] = {};

    const int arb = (lane & 7) + ((lane >> 3) & 1) * 8;
    const int ac  = (lane >> 4) * 8;
    const int brb = (lane & 7) + ((lane >> 4) & 1) * 8;
    const int bc  = ((lane >> 3) & 1) * 8;

    xload(xs,              Abase, Bbase, 0, tid); CPCOMMIT();
    xload(xs + XSTAGE,     Abase, Bbase, 1, tid); CPCOMMIT();
    xload(xs + 2 * XSTAGE, Abase, Bbase, 2, tid); CPCOMMIT();

    for (int ck = 0; ck < 16; ck++) {
        if (ck < 14)       CPWAIT(2);
        else if (ck == 14) CPWAIT(1);
        else               CPWAIT(0);
        __syncthreads();

        const int s = ck % 3;
        bf16* Ah = xs + s * XSTAGE;
        bf16* Al = Ah + XBUF;
        bf16* Bh = Al + XBUF;
        bf16* Bl = Bh + XBUF;

        #pragma unroll
        for (int k4 = 0; k4 < 4; k4++) {
            const int co = k4 * 16;
            unsigned aF[2][2][4];
            #pragma unroll
            for (int mb = 0; mb < 2; mb++) {
                int r = wm * 32 + mb * 16 + arb;
                ldsm4(aF[mb][0], Ah + r * XP + co + ac);
                ldsm4(aF[mb][1], Al + r * XP + co + ac);
            }
            unsigned bF[8][2][2];
            #pragma unroll
            for (int p = 0; p < 4; p++) {
                int r = wn * 64 + p * 16 + brb;
                unsigned t[4];
                ldsm4(t, Bh + r * XP + co + bc);
                bF[2*p][0][0]=t[0]; bF[2*p][0][1]=t[1]; bF[2*p+1][0][0]=t[2]; bF[2*p+1][0][1]=t[3];
                ldsm4(t, Bl + r * XP + co + bc);
                bF[2*p][1][0]=t[0]; bF[2*p][1][1]=t[1]; bF[2*p+1][1][0]=t[2]; bF[2*p+1][1][1]=t[3];
            }
            #pragma unroll
            for (int mb = 0; mb < 2; mb++)
                #pragma unroll
                for (int nb = 0; nb < 8; nb++) {
                    mma_bf16(acc[mb][nb], aF[mb][0], bF[nb][0]);  // hi*hi
                    mma_bf16(acc[mb][nb], aF[mb][0], bF[nb][1]);  // hi*lo
                    mma_bf16(acc[mb][nb], aF[mb][1], bF[nb][0]);  // lo*hi
                }
        }
        __syncthreads();

        if (ck + 3 < 16) { xload(xs + s * XSTAGE, Abase, Bbase, ck + 3, tid); CPCOMMIT(); }
    }

    #pragma unroll
    for (int mb = 0; mb < 2; mb++) {
        int r0 = mB * 128 + wm * 32 + mb * 16 + (lane >> 2);
        #pragma unroll
        for (int nb = 0; nb < 8; nb++) {
            int c0 = nB * 128 + wn * 64 + nb * 8 + 2 * (lane & 3);
            float b0 = bias[c0], b1 = bias[c0 + 1];
            size_t o0 = (size_t)r0 * GG + c0;
            size_t o1 = (size_t)(r0 + 8) * GG + c0;
            g_gx[o0]     = acc[mb][nb][0] + b0;
            g_gx[o0 + 1] = acc[mb][nb][1] + b1;
            g_gx[o1]     = acc[mb][nb][2] + b0;
            g_gx[o1 + 1] = acc[mb][nb][3] + b1;
        }
    }
}

// ---------------- persistent recurrence (512 threads, 4m x 4k warps) ----------------
// 128 CTAs x 512 thr. CTA ch owns h-cols [ch*8, ch*8+8) -> 32 gate rows in SMEM (fp16).
// Each warp: wm = warp&3 (batch block), wk = warp>>2 (16-kt K slice), computes ALL
// four n-blocks -> every A-fragment load is unique (no duplication). A = fp16 single
// plane; W = fp16 hi + lo*1024 (separate fp32 chains, descaled in epilogue).
#define WPITCH 1032
#define GSF    2112   // 64*33 floats per staging buffer
#define RSMEM  (64 * WPITCH * 2 + 4 * GSF * 4)   // 132096 + 33792 = 165888
__global__ __launch_bounds__(512, 1) void recur(int layer, float* __restrict__ lastout) {
    extern __shared__ __align__(16) unsigned char sm[];
    __half* sWh = (__half*)sm;                      // [32][WPITCH] hi
    __half* sWl = (__half*)(sm + 32 * WPITCH * 2);  // [32][WPITCH] lo*1024
    float* gs = (float*)(sm + 64 * WPITCH * 2);     // [4][64][33]
    __shared__ unsigned sbase;

    const int tid  = threadIdx.x;
    const int warp = tid >> 5, lane = tid & 31;
    const int wm = warp & 3, wk = warp >> 2;        // 4 m-blocks x 4 K-slices
    const int ch = blockIdx.x;
    const int j0 = ch * 8;
    const __half* W = layer ? g_whh1 : g_whh0;

    for (int idx = tid; idx < 32 * 128; idx += 512) {
        int n = idx >> 7, u = idx & 127;
        int g = (n >> 3) * 1024 + j0 + (n & 7);
        *(uint4*)(sWh + n * WPITCH + u * 8) = *(const uint4*)(W + (size_t)g * 2048 + u * 8);
        *(uint4*)(sWl + n * WPITCH + u * 8) = *(const uint4*)(W + (size_t)g * 2048 + 1024 + u * 8);
    }
    if (tid == 0) sbase = g_flags[ch];
    __syncthreads();
    const unsigned base = sbase;

    // consumer (GEMM) indices
    const int coff = wm * 8192 + lane * 4 + wk * 16 * 128;   // A base for this warp's K slice
    const int brow = (lane & 7) + ((lane >> 4) & 1) * 8;
    const int bcc  = ((lane >> 3) & 1) * 8;
    const __half* sWh_l0 = sWh + brow * WPITCH + bcc + wk * 16 * 16;          // rows 0-15
    const __half* sWh_l1 = sWh + (16 + brow) * WPITCH + bcc + wk * 16 * 16;   // rows 16-31
    const __half* sWl_l0 = sWl + brow * WPITCH + bcc + wk * 16 * 16;
    const __half* sWl_l1 = sWl + (16 + brow) * WPITCH + bcc + wk * 16 * 16;
    float* gw = gs + wk * GSF;
    const float ILO = 1.0f / 1024.0f;

    // writer (elementwise) indices: threads 0-255, each -> (b, col, col+1)
    const int b  = (tid & 255) >> 2;
    const int jp = tid & 3;
    const int col = j0 + 2 * jp;
    const int widx = (b >> 4) * 8192 + (col >> 4) * 128
                   + ((((b & 7) << 2) | ((col >> 1) & 3)) << 2)
                   + ((col >> 3) & 1) * 2 + ((b >> 3) & 1);

    float c0 = 0.0f, c1 = 0.0f;   // cell state (threads 0-255 only)

    for (int t = 0; t < TT; t++) {
        float2 gx0, gx1, gx2, gx3;
        if (tid < 256) {
            const float* gx = g_gx + ((size_t)t * 64 + b) * GG + col;
            gx0 = *(const float2*)(gx);
            gx1 = *(const float2*)(gx + 1024);
            gx2 = *(const float2*)(gx + 2048);
            gx3 = *(const float2*)(gx + 3072);
        }

        float accH[4][4] = {}, accL[4][4] = {};
        if (t > 0) {
            const unsigned* hf = g_hf[(t & 1) ^ 1] + coff;
            #pragma unroll 4
            for (int k = 0; k < 16; k++) {
                unsigned aH[4], b0h[4], b1h[4], b0l[4], b1l[4];
                ldg_cg4(aH, hf + k * 128);
                ldsm4(b0h, sWh_l0 + k * 16);
                ldsm4(b1h, sWh_l1 + k * 16);
                ldsm4(b0l, sWl_l0 + k * 16);
                ldsm4(b1l, sWl_l1 + k * 16);
                mma_f16(accH[0], aH, b0h[0], b0h[1]);
                mma_f16(accH[1], aH, b0h[2], b0h[3]);
                mma_f16(accH[2], aH, b1h[0], b1h[1]);
                mma_f16(accH[3], aH, b1h[2], b1h[3]);
                mma_f16(accL[0], aH, b0l[0], b0l[1]);
                mma_f16(accL[1], aH, b0l[2], b0l[3]);
                mma_f16(accL[2], aH, b1l[0], b1l[1]);
                mma_f16(accL[3], aH, b1l[2], b1l[3]);
            }
        }

        // stage gate partial sums (hi + lo/1024) to this K-slice's buffer [64][33]
        {
            int r = wm * 16 + (lane >> 2);
            #pragma unroll
            for (int nb = 0; nb < 4; nb++) {
                int c = nb * 8 + 2 * (lane & 3);
                gw[r * 33 + c]           = accH[nb][0] + accL[nb][0] * ILO;
                gw[r * 33 + c + 1]       = accH[nb][1] + accL[nb][1] * ILO;
                gw[(r + 8) * 33 + c]     = accH[nb][2] + accL[nb][2] * ILO;
                gw[(r + 8) * 33 + c + 1] = accH[nb][3] + accL[nb][3] * ILO;
            }
        }
        __syncthreads();

        // LSTM elementwise: threads 0-255, 2 cells each (cols col, col+1)
        if (tid < 256) {
            #define SUM4(off) (gs[(off)] + gs[GSF + (off)] + gs[2*GSF + (off)] + gs[3*GSF + (off)])
            float gi0 = SUM4(b * 33 + 2*jp)          + gx0.x;
            float gi1 = SUM4(b * 33 + 2*jp + 1)      + gx0.y;
            float gf0 = SUM4(b * 33 + 8 + 2*jp)      + gx1.x;
            float gf1 = SUM4(b * 33 + 8 + 2*jp + 1)  + gx1.y;
            float gg0 = SUM4(b * 33 + 16 + 2*jp)     + gx2.x;
            float gg1 = SUM4(b * 33 + 16 + 2*jp + 1) + gx2.y;
            float go0 = SUM4(b * 33 + 24 + 2*jp)     + gx3.x;
            float go1 = SUM4(b * 33 + 24 + 2*jp + 1) + gx3.y;
            #undef SUM4

            float i0 = sigf(gi0), f0 = sigf(gf0), G0 = tanhf(gg0), o0 = sigf(go0);
            float i1 = sigf(gi1), f1 = sigf(gf1), G1 = tanhf(gg1), o1 = sigf(go1);
            c0 = f0 * c0 + i0 * G0;
            c1 = f1 * c1 + i1 * G1;
            float hn0 = o0 * tanhf(c0);
            float hn1 = o1 * tanhf(c1);

            __half2 hh2 = __halves2half2(__float2half_rn(hn0), __float2half_rn(hn1));
            g_hf[t & 1][widx] = *(unsigned*)&hh2;
            if (layer == 0) {
                unsigned hiw, low;
                split2(hn0, hn1, hiw, low);
                bf16* ax = g_ax + ((size_t)t * 64 + b) * 2048 + col;
                *(unsigned*)ax          = hiw;
                *(unsigned*)(ax + 1024) = low;
            } else if (t == TT - 1) {
                lastout[b * HH + col]     = hn0;
                lastout[b * HH + col + 1] = hn1;
            }
        }

        // release: all threads' h stores ordered before flag; then hot-spin barrier.
        __threadfence();
        __syncthreads();
        const unsigned target = base + (unsigned)t + 1u;
        if (tid == 0) st_rel(&g_flags[ch], target);
        if (tid < 128) {
            while ((int)(ld_acq(&g_flags[tid]) - target) < 0) { }
        }
        __syncthreads();
        // no acquire fence needed: h reads use ld.cg (L2 is the coherence point)
    }
}

// ---------------- host launcher ----------------
extern "C" void kernel_launch(void* const* d_in, const int* in_sizes, int n_in,
                              void* d_out, int out_size) {
    (void)in_sizes; (void)n_in; (void)out_size;
    const float* x     = (const float*)d_in[0];
    const float* w_ih0 = (const float*)d_in[1];
    const float* w_hh0 = (const float*)d_in[2];
    const float* b_ih0 = (const float*)d_in[3];
    const float* b_hh0 = (const float*)d_in[4];
    const float* w_ih1 = (const float*)d_in[5];
    const float* w_hh1 = (const float*)d_in[6];
    const float* b_ih1 = (const float*)d_in[7];
    const float* b_hh1 = (const float*)d_in[8];
    const unsigned* m_ih0 = (const unsigned*)d_in[9];
    const unsigned* m_hh0 = (const unsigned*)d_in[10];
    const unsigned* m_ih1 = (const unsigned*)d_in[11];
    const unsigned* m_hh1 = (const unsigned*)d_in[12];
    float* out = (float*)d_out;

    cudaFuncSetAttribute(recur, cudaFuncAttributeMaxDynamicSharedMemorySize, RSMEM);
    cudaFuncSetAttribute(xgemm, cudaFuncAttributeMaxDynamicSharedMemorySize, XSMEM);

    prep_all<<<65537, 256>>>(w_ih0, m_ih0, w_hh0, m_hh0, w_ih1, m_ih1, w_hh1, m_hh1,
                             b_ih0, b_hh0, b_ih1, b_hh1);
    prep_ax<<<MTOT / 2, 256>>>(x);

    dim3 gemmGrid(GG / 128, MTOT / 128);   // (32, 256)

    xgemm<<<gemmGrid, 256, XSMEM>>>(0);
    recur<<<128, 512, RSMEM>>>(0, nullptr);   // also writes g_ax for layer 1

    xgemm<<<gemmGrid, 256, XSMEM>>>(1);
    recur<<<128, 512, RSMEM>>>(1, out);
}

// round 11
// speedup vs baseline: 2.1191x; 1.1115x over previous
#include <cuda_runtime.h>
#include <cuda_bf16.h>
#include <cuda_fp16.h>
#include <cstdint>

typedef __nv_bfloat16 bf16;

#define BSZ 64
#define TT  512
#define FF  1024
#define HH  1024
#define GG  4096
#define KK  1024
#define MTOT (TT*BSZ)   // 32768

// ---------------- device scratch ----------------
__device__ __align__(16) __half g_wih0[GG * 2 * KK];   // [G][hi | lo*1024] fp16 (xgemm)
__device__ __align__(16) __half g_wih1[GG * 2 * KK];
__device__ __align__(16) __half g_whh0[GG * 2 * KK];   // [G][hi | lo*1024] fp16 (recur)
__device__ __align__(16) __half g_whh1[GG * 2 * KK];
__device__ __align__(16) float  g_bias0[GG];
__device__ __align__(16) float  g_bias1[GG];
__device__ __align__(16) float  g_gx[(size_t)MTOT * GG];   // gates_x (512 MB)
__device__ __align__(16) __half g_ax[(size_t)MTOT * KK];   // fp16 A for xgemm (64 MB)
// h in mma-fragment layout (fp16x2, single plane):
//   u32 idx(wm, kt, lane, reg) = wm*8192 + kt*128 + lane*4 + reg
__device__ __align__(16) unsigned g_hf[2][32768];

// grid-barrier flags: monotonic, never reset (deterministic across graph replays)
__device__ volatile unsigned g_flags[128];

// ---------------- helpers ----------------
__device__ __forceinline__ void mma_f16(float acc[4], const unsigned a[4], unsigned b0, unsigned b1) {
    asm volatile(
        "mma.sync.aligned.m16n8k16.row.col.f32.f16.f16.f32 "
        "{%0,%1,%2,%3},{%4,%5,%6,%7},{%8,%9},{%0,%1,%2,%3};\n"
        : "+f"(acc[0]), "+f"(acc[1]), "+f"(acc[2]), "+f"(acc[3])
        : "r"(a[0]), "r"(a[1]), "r"(a[2]), "r"(a[3]), "r"(b0), "r"(b1));
}

__device__ __forceinline__ void ldsm4(unsigned r[4], const void* p) {
    unsigned addr = (unsigned)__cvta_generic_to_shared(p);
    asm volatile("ldmatrix.sync.aligned.m8n8.x4.shared.b16 {%0,%1,%2,%3},[%4];\n"
                 : "=r"(r[0]), "=r"(r[1]), "=r"(r[2]), "=r"(r[3]) : "r"(addr));
}

// L1-bypass vector load (h ping-pong: L2 is the coherence point)
__device__ __forceinline__ void ldg_cg4(unsigned r[4], const void* p) {
    asm volatile("ld.global.cg.v4.u32 {%0,%1,%2,%3}, [%4];\n"
                 : "=r"(r[0]), "=r"(r[1]), "=r"(r[2]), "=r"(r[3]) : "l"(p));
}

__device__ __forceinline__ void st_rel(volatile unsigned* p, unsigned v) {
    asm volatile("st.release.gpu.global.u32 [%0], %1;\n" :: "l"((void*)p), "r"(v) : "memory");
}
__device__ __forceinline__ unsigned ld_acq(volatile unsigned* p) {
    unsigned v;
    asm volatile("ld.acquire.gpu.global.u32 %0, [%1];\n" : "=r"(v) : "l"((void*)p) : "memory");
    return v;
}

__device__ __forceinline__ void cpa16(void* dst, const void* src) {
    unsigned d = (unsigned)__cvta_generic_to_shared(dst);
    asm volatile("cp.async.cg.shared.global [%0], [%1], 16;\n" :: "r"(d), "l"(src));
}
#define CPCOMMIT() asm volatile("cp.async.commit_group;\n")
#define CPWAIT(n)  asm volatile("cp.async.wait_group %0;\n" :: "n"(n))

__device__ __forceinline__ float sigf(float x) { return 1.0f / (1.0f + expf(-x)); }

// ---------------- prep: all weights + biases in ONE launch ----------------
// All W -> fp16 hi + (lo*1024) fp16. Masks are 32-bit words; nonzero = keep.
__global__ void prep_all(const float* __restrict__ w0, const unsigned* __restrict__ m0,
                         const float* __restrict__ w1, const unsigned* __restrict__ m1,
                         const float* __restrict__ w2, const unsigned* __restrict__ m2,
                         const float* __restrict__ w3, const unsigned* __restrict__ m3,
                         const float* __restrict__ bi0, const float* __restrict__ bh0,
                         const float* __restrict__ bi1, const float* __restrict__ bh1) {
    int blk = blockIdx.x;
    if (blk < 65536) {
        int which = blk >> 14;
        int idx = (blk & 16383) * 256 + threadIdx.x;
        const float*    w = (which == 0) ? w0 : (which == 1) ? w1 : (which == 2) ? w2 : w3;
        const unsigned* m = (which == 0) ? m0 : (which == 1) ? m1 : (which == 2) ? m2 : m3;
        __half* dst = (which == 0) ? g_wih0 : (which == 1) ? g_whh0 : (which == 2) ? g_wih1 : g_whh1;
        int g = idx >> 10, k = idx & 1023;
        float v = (m[idx] != 0u) ? w[idx] : 0.0f;
        __half hi = __float2half_rn(v);
        float r = (v - __half2float(hi)) * 1024.0f;
        dst[(size_t)g * 2048 + k]        = hi;
        dst[(size_t)g * 2048 + 1024 + k] = __float2half_rn(r);
    } else {
        for (int i = threadIdx.x; i < GG; i += 256) {
            g_bias0[i] = bi0[i] + bh0[i];
            g_bias1[i] = bi1[i] + bh1[i];
        }
    }
}

// ---------------- prep: x -> g_ax fp16 rows (m = t*64 + b) ----------------
__global__ void prep_ax(const float* __restrict__ x) {
    int m = blockIdx.x * 2 + (threadIdx.x >> 7);
    int c = (threadIdx.x & 127) * 8;
    const float* src = x + ((size_t)(m & 63) * TT + (m >> 6)) * FF + c;
    float4 v0 = *(const float4*)src;
    float4 v1 = *(const float4*)(src + 4);
    __half2 h0 = __halves2half2(__float2half_rn(v0.x), __float2half_rn(v0.y));
    __half2 h1 = __halves2half2(__float2half_rn(v0.z), __float2half_rn(v0.w));
    __half2 h2 = __halves2half2(__float2half_rn(v1.x), __float2half_rn(v1.y));
    __half2 h3 = __halves2half2(__float2half_rn(v1.z), __float2half_rn(v1.w));
    *(uint4*)(g_ax + (size_t)m * 1024 + c) =
        make_uint4(*(unsigned*)&h0, *(unsigned*)&h1, *(unsigned*)&h2, *(unsigned*)&h3);
}

// ---------------- big input GEMM: gates_x = A @ W^T + bias (fp16 2-product) ----------------
// A = g_ax [32768][1024] fp16; W = fp16 hi + lo*1024 [4096][2048]; C = g_gx fp32.
// CTA tile 128x128, 8 warps 4(m)x2(n), warp tile 32x64.
// K chunks of 64 (128-B rows), cp.async THREE-stage pipeline. Buffers: A, Bh, Bl.
#define XP 72                 // smem row pitch (fp16)
#define XBUF (128 * XP)       // one buffer (elems)
#define XSTAGE (3 * XBUF)     // A, Bh, Bl
#define XSMEM (3 * XSTAGE * 2)  // bytes = 165888

__device__ __forceinline__ void xload(__half* st, const __half* Abase, const __half* Bbase,
                                      int ck, int tid) {
    #pragma unroll
    for (int i = 0; i < 4; i++) {
        int j = tid + i * 256;                 // [0,1024)
        int row = j >> 3, seg = j & 7;
        const __half* as = Abase + (size_t)row * 1024 + ck * 64 + seg * 8;
        const __half* bs = Bbase + (size_t)row * 2048 + ck * 64 + seg * 8;
        __half* d = st + row * XP + seg * 8;
        cpa16(d,          as);
        cpa16(d + XBUF,   bs);
        cpa16(d + 2*XBUF, bs + 1024);
    }
}

__global__ __launch_bounds__(256) void xgemm(int layer) {
    extern __shared__ __align__(16) __half xs[];
    const __half* W   = layer ? g_wih1 : g_wih0;
    const float* bias = layer ? g_bias1 : g_bias0;

    const int tid  = threadIdx.x;
    const int warp = tid >> 5, lane = tid & 31;
    const int wm = warp & 3, wn = warp >> 2;
    const int mB = blockIdx.y, nB = blockIdx.x;
    const __half* Abase = g_ax + (size_t)(mB * 128) * 1024;
    const __half* Bbase = W   + (size_t)(nB * 128) * 2048;

    float accH[2][8][4] = {}, accL[2][8][4] = {};

    const int arb = (lane & 7) + ((lane >> 3) & 1) * 8;
    const int ac  = (lane >> 4) * 8;
    const int brb = (lane & 7) + ((lane >> 4) & 1) * 8;
    const int bc  = ((lane >> 3) & 1) * 8;

    xload(xs,              Abase, Bbase, 0, tid); CPCOMMIT();
    xload(xs + XSTAGE,     Abase, Bbase, 1, tid); CPCOMMIT();
    xload(xs + 2 * XSTAGE, Abase, Bbase, 2, tid); CPCOMMIT();

    for (int ck = 0; ck < 16; ck++) {
        if (ck < 14)       CPWAIT(2);
        else if (ck == 14) CPWAIT(1);
        else               CPWAIT(0);
        __syncthreads();

        const int s = ck % 3;
        __half* Aa = xs + s * XSTAGE;
        __half* Bh = Aa + XBUF;
        __half* Bl = Bh + XBUF;

        #pragma unroll
        for (int k4 = 0; k4 < 4; k4++) {
            const int co = k4 * 16;
            unsigned aF[2][4];
            #pragma unroll
            for (int mb = 0; mb < 2; mb++) {
                int r = wm * 32 + mb * 16 + arb;
                ldsm4(aF[mb], Aa + r * XP + co + ac);
            }
            unsigned bFh[8][2], bFl[8][2];
            #pragma unroll
            for (int p = 0; p < 4; p++) {
                int r = wn * 64 + p * 16 + brb;
                unsigned t[4];
                ldsm4(t, Bh + r * XP + co + bc);
                bFh[2*p][0]=t[0]; bFh[2*p][1]=t[1]; bFh[2*p+1][0]=t[2]; bFh[2*p+1][1]=t[3];
                ldsm4(t, Bl + r * XP + co + bc);
                bFl[2*p][0]=t[0]; bFl[2*p][1]=t[1]; bFl[2*p+1][0]=t[2]; bFl[2*p+1][1]=t[3];
            }
            #pragma unroll
            for (int mb = 0; mb < 2; mb++)
                #pragma unroll
                for (int nb = 0; nb < 8; nb++) {
                    mma_f16(accH[mb][nb], aF[mb], bFh[nb][0], bFh[nb][1]);
                    mma_f16(accL[mb][nb], aF[mb], bFl[nb][0], bFl[nb][1]);
                }
        }
        __syncthreads();

        if (ck + 3 < 16) { xload(xs + s * XSTAGE, Abase, Bbase, ck + 3, tid); CPCOMMIT(); }
    }

    const float ILO = 1.0f / 1024.0f;
    #pragma unroll
    for (int mb = 0; mb < 2; mb++) {
        int r0 = mB * 128 + wm * 32 + mb * 16 + (lane >> 2);
        #pragma unroll
        for (int nb = 0; nb < 8; nb++) {
            int c0 = nB * 128 + wn * 64 + nb * 8 + 2 * (lane & 3);
            float b0 = bias[c0], b1 = bias[c0 + 1];
            size_t o0 = (size_t)r0 * GG + c0;
            size_t o1 = (size_t)(r0 + 8) * GG + c0;
            g_gx[o0]     = accH[mb][nb][0] + accL[mb][nb][0] * ILO + b0;
            g_gx[o0 + 1] = accH[mb][nb][1] + accL[mb][nb][1] * ILO + b1;
            g_gx[o1]     = accH[mb][nb][2] + accL[mb][nb][2] * ILO + b0;
            g_gx[o1 + 1] = accH[mb][nb][3] + accL[mb][nb][3] * ILO + b1;
        }
    }
}

// ---------------- persistent recurrence (512 threads, 4m x 4k warps) ----------------
// 128 CTAs x 512 thr. CTA ch owns h-cols [ch*8, ch*8+8) -> 32 gate rows in SMEM (fp16).
// Each warp: wm = warp&3 (batch block), wk = warp>>2 (16-kt K slice), computes ALL
// four n-blocks -> every A-fragment load is unique. A = fp16 single plane;
// W = fp16 hi + lo*1024 (separate fp32 chains, descaled in epilogue).
#define WPITCH 1032
#define GSF    2112   // 64*33 floats per staging buffer
#define RSMEM  (64 * WPITCH * 2 + 4 * GSF * 4)   // 132096 + 33792 = 165888
__global__ __launch_bounds__(512, 1) void recur(int layer, float* __restrict__ lastout) {
    extern __shared__ __align__(16) unsigned char sm[];
    __half* sWh = (__half*)sm;                      // [32][WPITCH] hi
    __half* sWl = (__half*)(sm + 32 * WPITCH * 2);  // [32][WPITCH] lo*1024
    float* gs = (float*)(sm + 64 * WPITCH * 2);     // [4][64][33]
    __shared__ unsigned sbase;

    const int tid  = threadIdx.x;
    const int warp = tid >> 5, lane = tid & 31;
    const int wm = warp & 3, wk = warp >> 2;        // 4 m-blocks x 4 K-slices
    const int ch = blockIdx.x;
    const int j0 = ch * 8;
    const __half* W = layer ? g_whh1 : g_whh0;

    for (int idx = tid; idx < 32 * 128; idx += 512) {
        int n = idx >> 7, u = idx & 127;
        int g = (n >> 3) * 1024 + j0 + (n & 7);
        *(uint4*)(sWh + n * WPITCH + u * 8) = *(const uint4*)(W + (size_t)g * 2048 + u * 8);
        *(uint4*)(sWl + n * WPITCH + u * 8) = *(const uint4*)(W + (size_t)g * 2048 + 1024 + u * 8);
    }
    if (tid == 0) sbase = g_flags[ch];
    __syncthreads();
    const unsigned base = sbase;

    // consumer (GEMM) indices
    const int coff = wm * 8192 + lane * 4 + wk * 16 * 128;   // A base for this warp's K slice
    const int brow = (lane & 7) + ((lane >> 4) & 1) * 8;
    const int bcc  = ((lane >> 3) & 1) * 8;
    const __half* sWh_l0 = sWh + brow * WPITCH + bcc + wk * 16 * 16;          // rows 0-15
    const __half* sWh_l1 = sWh + (16 + brow) * WPITCH + bcc + wk * 16 * 16;   // rows 16-31
    const __half* sWl_l0 = sWl + brow * WPITCH + bcc + wk * 16 * 16;
    const __half* sWl_l1 = sWl + (16 + brow) * WPITCH + bcc + wk * 16 * 16;
    float* gw = gs + wk * GSF;
    const float ILO = 1.0f / 1024.0f;

    // writer (elementwise) indices: threads 0-255, each -> (b, col, col+1)
    const int b  = (tid & 255) >> 2;
    const int jp = tid & 3;
    const int col = j0 + 2 * jp;
    const int widx = (b >> 4) * 8192 + (col >> 4) * 128
                   + ((((b & 7) << 2) | ((col >> 1) & 3)) << 2)
                   + ((col >> 3) & 1) * 2 + ((b >> 3) & 1);

    float c0 = 0.0f, c1 = 0.0f;   // cell state (threads 0-255 only)

    for (int t = 0; t < TT; t++) {
        float2 gx0, gx1, gx2, gx3;
        if (tid < 256) {
            const float* gx = g_gx + ((size_t)t * 64 + b) * GG + col;
            gx0 = *(const float2*)(gx);
            gx1 = *(const float2*)(gx + 1024);
            gx2 = *(const float2*)(gx + 2048);
            gx3 = *(const float2*)(gx + 3072);
        }

        float accH[4][4] = {}, accL[4][4] = {};
        if (t > 0) {
            const unsigned* hf = g_hf[(t & 1) ^ 1] + coff;
            #pragma unroll 4
            for (int k = 0; k < 16; k++) {
                unsigned aH[4], b0h[4], b1h[4], b0l[4], b1l[4];
                ldg_cg4(aH, hf + k * 128);
                ldsm4(b0h, sWh_l0 + k * 16);
                ldsm4(b1h, sWh_l1 + k * 16);
                ldsm4(b0l, sWl_l0 + k * 16);
                ldsm4(b1l, sWl_l1 + k * 16);
                mma_f16(accH[0], aH, b0h[0], b0h[1]);
                mma_f16(accH[1], aH, b0h[2], b0h[3]);
                mma_f16(accH[2], aH, b1h[0], b1h[1]);
                mma_f16(accH[3], aH, b1h[2], b1h[3]);
                mma_f16(accL[0], aH, b0l[0], b0l[1]);
                mma_f16(accL[1], aH, b0l[2], b0l[3]);
                mma_f16(accL[2], aH, b1l[0], b1l[1]);
                mma_f16(accL[3], aH, b1l[2], b1l[3]);
            }
        }

        // stage gate partial sums (hi + lo/1024) to this K-slice's buffer [64][33]
        {
            int r = wm * 16 + (lane >> 2);
            #pragma unroll
            for (int nb = 0; nb < 4; nb++) {
                int c = nb * 8 + 2 * (lane & 3);
                gw[r * 33 + c]           = accH[nb][0] + accL[nb][0] * ILO;
                gw[r * 33 + c + 1]       = accH[nb][1] + accL[nb][1] * ILO;
                gw[(r + 8) * 33 + c]     = accH[nb][2] + accL[nb][2] * ILO;
                gw[(r + 8) * 33 + c + 1] = accH[nb][3] + accL[nb][3] * ILO;
            }
        }
        __syncthreads();

        // LSTM elementwise: threads 0-255, 2 cells each (cols col, col+1)
        if (tid < 256) {
            #define SUM4(off) (gs[(off)] + gs[GSF + (off)] + gs[2*GSF + (off)] + gs[3*GSF + (off)])
            float gi0 = SUM4(b * 33 + 2*jp)          + gx0.x;
            float gi1 = SUM4(b * 33 + 2*jp + 1)      + gx0.y;
            float gf0 = SUM4(b * 33 + 8 + 2*jp)      + gx1.x;
            float gf1 = SUM4(b * 33 + 8 + 2*jp + 1)  + gx1.y;
            float gg0 = SUM4(b * 33 + 16 + 2*jp)     + gx2.x;
            float gg1 = SUM4(b * 33 + 16 + 2*jp + 1) + gx2.y;
            float go0 = SUM4(b * 33 + 24 + 2*jp)     + gx3.x;
            float go1 = SUM4(b * 33 + 24 + 2*jp + 1) + gx3.y;
            #undef SUM4

            float i0 = sigf(gi0), f0 = sigf(gf0), G0 = tanhf(gg0), o0 = sigf(go0);
            float i1 = sigf(gi1), f1 = sigf(gf1), G1 = tanhf(gg1), o1 = sigf(go1);
            c0 = f0 * c0 + i0 * G0;
            c1 = f1 * c1 + i1 * G1;
            float hn0 = o0 * tanhf(c0);
            float hn1 = o1 * tanhf(c1);

            __half2 hh2 = __halves2half2(__float2half_rn(hn0), __float2half_rn(hn1));
            g_hf[t & 1][widx] = *(unsigned*)&hh2;
            if (layer == 0) {
                *(unsigned*)(g_ax + ((size_t)t * 64 + b) * 1024 + col) = *(unsigned*)&hh2;
            } else if (t == TT - 1) {
                lastout[b * HH + col]     = hn0;
                lastout[b * HH + col + 1] = hn1;
            }
        }

        // release: all threads' h stores ordered before flag; then hot-spin barrier.
        __threadfence();
        __syncthreads();
        const unsigned target = base + (unsigned)t + 1u;
        if (tid == 0) st_rel(&g_flags[ch], target);
        if (tid < 128) {
            while ((int)(ld_acq(&g_flags[tid]) - target) < 0) { }
        }
        __syncthreads();
        // no acquire fence needed: h reads use ld.cg (L2 is the coherence point)
    }
}

// ---------------- host launcher ----------------
extern "C" void kernel_launch(void* const* d_in, const int* in_sizes, int n_in,
                              void* d_out, int out_size) {
    (void)in_sizes; (void)n_in; (void)out_size;
    const float* x     = (const float*)d_in[0];
    const float* w_ih0 = (const float*)d_in[1];
    const float* w_hh0 = (const float*)d_in[2];
    const float* b_ih0 = (const float*)d_in[3];
    const float* b_hh0 = (const float*)d_in[4];
    const float* w_ih1 = (const float*)d_in[5];
    const float* w_hh1 = (const float*)d_in[6];
    const float* b_ih1 = (const float*)d_in[7];
    const float* b_hh1 = (const float*)d_in[8];
    const unsigned* m_ih0 = (const unsigned*)d_in[9];
    const unsigned* m_hh0 = (const unsigned*)d_in[10];
    const unsigned* m_ih1 = (const unsigned*)d_in[11];
    const unsigned* m_hh1 = (const unsigned*)d_in[12];
    float* out = (float*)d_out;

    cudaFuncSetAttribute(recur, cudaFuncAttributeMaxDynamicSharedMemorySize, RSMEM);
    cudaFuncSetAttribute(xgemm, cudaFuncAttributeMaxDynamicSharedMemorySize, XSMEM);

    prep_all<<<65537, 256>>>(w_ih0, m_ih0, w_hh0, m_hh0, w_ih1, m_ih1, w_hh1, m_hh1,
                             b_ih0, b_hh0, b_ih1, b_hh1);
    prep_ax<<<MTOT / 2, 256>>>(x);

    dim3 gemmGrid(GG / 128, MTOT / 128);   // (32, 256)

    xgemm<<<gemmGrid, 256, XSMEM>>>(0);
    recur<<<128, 512, RSMEM>>>(0, nullptr);   // also writes g_ax for layer 1

    xgemm<<<gemmGrid, 256, XSMEM>>>(1);
    recur<<<128, 512, RSMEM>>>(1, out);
}